// round 12
// baseline (speedup 1.0000x reference)
#include <cuda_runtime.h>
#include <cuda_fp16.h>
#include <cstdint>

// Problem dims
#define S_LEN 4096
#define D_DIM 2048
#define H_NUM 16
#define F_DIM 8192
#define QKV_LD 6144

// ---------------------------------------------------------------------------
// Scratch (allocation is banned; use device globals)
// ---------------------------------------------------------------------------
__device__ __half g_xh[S_LEN * D_DIM];
__device__ __half g_qkvh[S_LEN * QKV_LD];
__device__ __half g_headsh[S_LEN * D_DIM];
__device__ float  g_proj[S_LEN * D_DIM];
__device__ __half g_lnh[S_LEN * D_DIM];
__device__ __half g_h1h[S_LEN * F_DIM];
// transposed fp16 weights, [N, K] row-major
__device__ __half g_wqkvt[3 * D_DIM * D_DIM];
__device__ float  g_bqkv[QKV_LD];
__device__ __half g_wpt[D_DIM * D_DIM];
__device__ __half g_w1t[F_DIM * D_DIM];
__device__ __half g_w2t[D_DIM * F_DIM];

// ---------------------------------------------------------------------------
// Portable PTX helpers (sm_80-level; tcgen05 is gated off on plain sm_103)
// ---------------------------------------------------------------------------
__device__ __forceinline__ uint32_t smem_u32(const void* p) {
    uint32_t a;
    asm("{ .reg .u64 t; cvta.to.shared.u64 t, %1; cvt.u32.u64 %0, t; }"
        : "=r"(a) : "l"(p));
    return a;
}

__device__ __forceinline__ uint32_t packh2(float a, float b) {
    __half2 h = __floats2half2_rn(a, b);
    return *reinterpret_cast<uint32_t*>(&h);
}

__device__ __forceinline__ void mma_f16(float* c, const uint32_t* a,
                                        uint32_t b0, uint32_t b1) {
    asm volatile(
        "mma.sync.aligned.m16n8k16.row.col.f32.f16.f16.f32 "
        "{%0,%1,%2,%3}, {%4,%5,%6,%7}, {%8,%9}, {%0,%1,%2,%3};"
        : "+f"(c[0]), "+f"(c[1]), "+f"(c[2]), "+f"(c[3])
        : "r"(a[0]), "r"(a[1]), "r"(a[2]), "r"(a[3]), "r"(b0), "r"(b1));
}

// .cg: bypass L1, stage via L2 only (streamed GEMM operands)
__device__ __forceinline__ void cp16cg(uint32_t saddr, const void* g) {
    asm volatile("cp.async.cg.shared.global [%0], [%1], 16;" :: "r"(saddr), "l"(g));
}
__device__ __forceinline__ void cp_commit() {
    asm volatile("cp.async.commit_group;" ::: "memory");
}
template <int N>
__device__ __forceinline__ void cp_wait() {
    asm volatile("cp.async.wait_group %0;" :: "n"(N) : "memory");
}

__device__ __forceinline__ void ldm_x4(uint32_t* r, uint32_t addr) {
    asm volatile("ldmatrix.sync.aligned.m8n8.x4.shared.b16 {%0,%1,%2,%3}, [%4];"
        : "=r"(r[0]), "=r"(r[1]), "=r"(r[2]), "=r"(r[3]) : "r"(addr));
}

__device__ __forceinline__ void ldm_x4_trans(uint32_t* r, uint32_t addr) {
    asm volatile("ldmatrix.sync.aligned.m8n8.x4.trans.shared.b16 {%0,%1,%2,%3}, [%4];"
        : "=r"(r[0]), "=r"(r[1]), "=r"(r[2]), "=r"(r[3]) : "r"(addr));
}

// ---------------------------------------------------------------------------
// fp16 warp-MMA GEMM, CTA 128x128, warp tile 32x64, BK=64, 2-stage cp.async.
// Round-9 2D-grid rasterization (row-major wave order; grouped raster
// regressed in R10/R11).
//   EPI 0: +bias   EPI 1: +bias+res(fp32)   EPI 2: relu(+bias)
//   OH: 1 -> half output, 0 -> fp32 output
// smem row stride 72 halves (144B): ldmatrix conflict-free.
// ---------------------------------------------------------------------------
#define GSTR 72
#define STAGE_HALVES (2 * 128 * GSTR)            // A + B per stage
#define GEMM_SMEM_BYTES (2 * STAGE_HALVES * 2)   // 73728

template <int EPI, int OH>
__global__ void __launch_bounds__(256) gemm_h_kernel(
    const __half* __restrict__ A, const __half* __restrict__ Bt,
    const float* __restrict__ bias, const float* __restrict__ res,
    void* __restrict__ Cv, int M, int N, int K)
{
    extern __shared__ __half sh[];
    const uint32_t sbase = smem_u32(sh);

    float*  Cf = (float*)Cv;
    __half* Ch = (__half*)Cv;

    const int tid = threadIdx.x, lane = tid & 31, w = tid >> 5;
    const int wm = w >> 1, wn = w & 1;     // 4m x 2n; warp tile 32x64
    const int bm = blockIdx.y * 128, bn = blockIdx.x * 128;
    const int nk = K >> 6;

    const int crow = tid >> 3;        // 0..31
    const int ccol = (tid & 7) * 8;   // halves within 64-wide row

    auto load_stage = [&](int kt, int slot) {
        const int k0 = kt << 6;
        const uint32_t sa = sbase + slot * STAGE_HALVES * 2;
        const uint32_t sb = sa + 128 * GSTR * 2;
#pragma unroll
        for (int it = 0; it < 4; it++) {
            const int r = crow + it * 32;
            cp16cg(sa + (r * GSTR + ccol) * 2, A  + (size_t)(bm + r) * K + k0 + ccol);
            cp16cg(sb + (r * GSTR + ccol) * 2, Bt + (size_t)(bn + r) * K + k0 + ccol);
        }
    };

    float acc[2][8][4];
#pragma unroll
    for (int i = 0; i < 2; i++)
#pragma unroll
        for (int j = 0; j < 8; j++)
#pragma unroll
            for (int r = 0; r < 4; r++) acc[i][j][r] = 0.f;

    load_stage(0, 0); cp_commit();

    const int frow = lane & 15;
    const int fcol = (lane >> 4) * 8;

    for (int kt = 0; kt < nk; kt++) {
        cp_wait<0>();
        __syncthreads();
        if (kt + 1 < nk) { load_stage(kt + 1, (kt + 1) & 1); cp_commit(); }

        const uint32_t sa = sbase + (kt & 1) * STAGE_HALVES * 2;
        const uint32_t sb = sa + 128 * GSTR * 2;

#pragma unroll
        for (int kk = 0; kk < 4; kk++) {
            uint32_t af[2][4], bf[4][4];
#pragma unroll
            for (int i = 0; i < 2; i++)
                ldm_x4(af[i], sa + ((wm * 32 + i * 16 + frow) * GSTR + kk * 16 + fcol) * 2);
#pragma unroll
            for (int j2 = 0; j2 < 4; j2++)
                ldm_x4(bf[j2], sb + ((wn * 64 + j2 * 16 + frow) * GSTR + kk * 16 + fcol) * 2);
#pragma unroll
            for (int i = 0; i < 2; i++)
#pragma unroll
                for (int j = 0; j < 8; j++)
                    mma_f16(acc[i][j], af[i], bf[j >> 1][j & 1], bf[j >> 1][2 + (j & 1)]);
        }
    }

    // epilogue
#pragma unroll
    for (int i = 0; i < 2; i++) {
#pragma unroll
        for (int j = 0; j < 8; j++) {
            const int row = bm + wm * 32 + i * 16 + (lane >> 2);
            const int col = bn + wn * 64 + j * 8 + (lane & 3) * 2;
            const float2 bv = *(const float2*)(bias + col);
#pragma unroll
            for (int hf = 0; hf < 2; hf++) {
                const int r = row + hf * 8;
                float vx = acc[i][j][hf * 2 + 0] + bv.x;
                float vy = acc[i][j][hf * 2 + 1] + bv.y;
                if (EPI == 1) {
                    float2 rv = *(const float2*)(res + (size_t)r * N + col);
                    vx += rv.x; vy += rv.y;
                }
                if (EPI == 2) { vx = fmaxf(vx, 0.f); vy = fmaxf(vy, 0.f); }
                if (OH) {
                    *(uint32_t*)(Ch + (size_t)r * N + col) = packh2(vx, vy);
                } else {
                    float2 o = { vx, vy };
                    *(float2*)(Cf + (size_t)r * N + col) = o;
                }
            }
        }
    }
}

// ---------------------------------------------------------------------------
// fp32 -> fp16 bulk convert
// ---------------------------------------------------------------------------
__global__ void __launch_bounds__(256) f2h_kernel(
    const float* __restrict__ in, __half* __restrict__ out)
{
    const size_t i = ((size_t)blockIdx.x * 256 + threadIdx.x) * 8;
    float4 a = *(const float4*)(in + i);
    float4 b = *(const float4*)(in + i + 4);
    uint4 o;
    o.x = packh2(a.x, a.y); o.y = packh2(a.z, a.w);
    o.z = packh2(b.x, b.y); o.w = packh2(b.z, b.w);
    *(uint4*)(out + i) = o;
}

// bias concat for fused QKV
__global__ void bias_concat_kernel(const float* __restrict__ bq,
                                   const float* __restrict__ bk,
                                   const float* __restrict__ bv,
                                   float* __restrict__ out)
{
    const int i = blockIdx.x * 256 + threadIdx.x;
    float v = (i < 2048) ? bq[i] : (i < 4096) ? bk[i - 2048] : bv[i - 4096];
    out[i] = v;
}

// ---------------------------------------------------------------------------
// Fused QKV weight transpose: [H,D,128] x3 -> stacked fp16 [6144, 2048].
// ---------------------------------------------------------------------------
__global__ void __launch_bounds__(256) transpose_qkv_kernel(
    const float* __restrict__ Wq, const float* __restrict__ Wk,
    const float* __restrict__ Wv, __half* __restrict__ out)
{
    __shared__ float t[32][33];
    const int z = blockIdx.z, which = z >> 4, hh = z & 15;
    const float* in = (which == 0) ? Wq : (which == 1) ? Wk : Wv;
    in  += (size_t)hh * D_DIM * 128;
    out += (size_t)which * D_DIM * D_DIM + (size_t)hh * 128 * D_DIM;
    const int k0 = blockIdx.y * 32;
    const int n0 = blockIdx.x * 32;
#pragma unroll
    for (int i = 0; i < 32; i += 8)
        t[threadIdx.y + i][threadIdx.x] =
            in[(size_t)(k0 + threadIdx.y + i) * 128 + n0 + threadIdx.x];
    __syncthreads();
#pragma unroll
    for (int i = 0; i < 32; i += 8)
        out[(size_t)(n0 + threadIdx.y + i) * D_DIM + k0 + threadIdx.x] =
            __float2half_rn(t[threadIdx.x][threadIdx.y + i]);
}

// ---------------------------------------------------------------------------
// Transpose fp32 [K,N] -> fp16 [N,K]. block (32, 8).
// ---------------------------------------------------------------------------
__global__ void __launch_bounds__(256) transpose_h_kernel(
    const float* __restrict__ in, __half* __restrict__ out,
    int K, int N, long inz, long outz)
{
    __shared__ float t[32][33];
    in  += (size_t)blockIdx.z * inz;
    out += (size_t)blockIdx.z * outz;
    const int k0 = blockIdx.y * 32;
    const int n0 = blockIdx.x * 32;
#pragma unroll
    for (int i = 0; i < 32; i += 8)
        t[threadIdx.y + i][threadIdx.x] =
            in[(size_t)(k0 + threadIdx.y + i) * N + n0 + threadIdx.x];
    __syncthreads();
#pragma unroll
    for (int i = 0; i < 32; i += 8)
        out[(size_t)(n0 + threadIdx.y + i) * K + k0 + threadIdx.x] =
            __float2half_rn(t[threadIdx.x][threadIdx.y + i]);
}

// ---------------------------------------------------------------------------
// Flash attention, fp16 mma, FA2-style (round-9 proven version).
// V row-major; PV B-fragments via ldmatrix.x4.trans. Single-buffer K/V,
// smem 69.6 KB -> 2 CTAs/SM.
// ---------------------------------------------------------------------------
#define QS_STR 136
#define KS_STR 136
#define VS_STR 136
#define FA_SMEM_BYTES ((128 * QS_STR + 64 * KS_STR + 64 * VS_STR) * 2)  // 69632

__global__ void __launch_bounds__(256) flash_attn_h_kernel(
    const __half* __restrict__ qkv, __half* __restrict__ heads)
{
    extern __shared__ __half smh[];
    __half* Qs  = smh;
    __half* Ks  = Qs + 128 * QS_STR;
    __half* Vs  = Ks + 64 * KS_STR;
    const uint32_t* Ks32 = (const uint32_t*)Ks;
    const uint32_t* Qs32 = (const uint32_t*)Qs;
    const uint32_t vbase = smem_u32(Vs);

    const __half* qb = qkv;
    const __half* kb = qkv + 2048;
    const __half* vb = qkv + 4096;

    const int h   = blockIdx.y;
    const int q0  = blockIdx.x * 128;
    const int tid = threadIdx.x, lane = tid & 31, w = tid >> 5;
    const int rq = lane >> 2, kq = lane & 3;
    const float scale = 0.08838834764831845f;

    {
        int idx = tid * 8;
#pragma unroll
        for (int it = 0; it < 8; it++) {
            int r = idx >> 7, c = idx & 127;
            *(uint4*)(Qs + r * QS_STR + c) =
                *(const uint4*)(qb + (size_t)(q0 + r) * QKV_LD + h * 128 + c);
            idx += 2048;
        }
    }
    __syncthreads();

    uint32_t qf[8][4];
    {
        const int r = w * 16 + rq;
#pragma unroll
        for (int ks = 0; ks < 8; ks++) {
            qf[ks][0] = Qs32[r * 68 + ks * 8 + kq];
            qf[ks][1] = Qs32[(r + 8) * 68 + ks * 8 + kq];
            qf[ks][2] = Qs32[r * 68 + ks * 8 + 4 + kq];
            qf[ks][3] = Qs32[(r + 8) * 68 + ks * 8 + 4 + kq];
        }
    }

    float O[16][4];
#pragma unroll
    for (int j = 0; j < 16; j++)
#pragma unroll
        for (int r = 0; r < 4; r++) O[j][r] = 0.f;
    float m0 = -1e30f, m1 = -1e30f, l0 = 0.f, l1 = 0.f;

    const uint32_t vrow = lane & 15;
    const uint32_t vcol = (lane >> 4) * 8;

    for (int kblk = 0; kblk < 64; kblk++) {
        {
            int idx = tid * 8;
#pragma unroll
            for (int it = 0; it < 4; it++) {
                int r = idx >> 7, c = idx & 127;
                *(uint4*)(Ks + r * KS_STR + c) =
                    *(const uint4*)(kb + (size_t)(kblk * 64 + r) * QKV_LD + h * 128 + c);
                *(uint4*)(Vs + r * VS_STR + c) =
                    *(const uint4*)(vb + (size_t)(kblk * 64 + r) * QKV_LD + h * 128 + c);
                idx += 2048;
            }
        }
        __syncthreads();

        float facc[8][4];
#pragma unroll
        for (int j = 0; j < 8; j++)
#pragma unroll
            for (int r = 0; r < 4; r++) facc[j][r] = 0.f;
#pragma unroll
        for (int ks = 0; ks < 8; ks++) {
#pragma unroll
            for (int j = 0; j < 8; j++) {
                const int n = j * 8 + rq;
                uint32_t b0 = Ks32[n * 68 + ks * 8 + kq];
                uint32_t b1 = Ks32[n * 68 + ks * 8 + 4 + kq];
                mma_f16(facc[j], qf[ks], b0, b1);
            }
        }

        float mx0 = -1e30f, mx1 = -1e30f;
#pragma unroll
        for (int j = 0; j < 8; j++) {
            facc[j][0] *= scale; facc[j][1] *= scale;
            facc[j][2] *= scale; facc[j][3] *= scale;
            mx0 = fmaxf(mx0, fmaxf(facc[j][0], facc[j][1]));
            mx1 = fmaxf(mx1, fmaxf(facc[j][2], facc[j][3]));
        }
        mx0 = fmaxf(mx0, __shfl_xor_sync(0xffffffffu, mx0, 1));
        mx0 = fmaxf(mx0, __shfl_xor_sync(0xffffffffu, mx0, 2));
        mx1 = fmaxf(mx1, __shfl_xor_sync(0xffffffffu, mx1, 1));
        mx1 = fmaxf(mx1, __shfl_xor_sync(0xffffffffu, mx1, 2));
        const float mn0 = fmaxf(m0, mx0), mn1 = fmaxf(m1, mx1);

        uint32_t ph0[8], ph1[8];
        float ls0 = 0.f, ls1 = 0.f;
#pragma unroll
        for (int j = 0; j < 8; j++) {
            float p0 = __expf(facc[j][0] - mn0);
            float p1 = __expf(facc[j][1] - mn0);
            float p2 = __expf(facc[j][2] - mn1);
            float p3 = __expf(facc[j][3] - mn1);
            ph0[j] = packh2(p0, p1);
            ph1[j] = packh2(p2, p3);
            ls0 += p0 + p1; ls1 += p2 + p3;
        }
        ls0 += __shfl_xor_sync(0xffffffffu, ls0, 1);
        ls0 += __shfl_xor_sync(0xffffffffu, ls0, 2);
        ls1 += __shfl_xor_sync(0xffffffffu, ls1, 1);
        ls1 += __shfl_xor_sync(0xffffffffu, ls1, 2);

        const float a0 = __expf(m0 - mn0), a1 = __expf(m1 - mn1);
        l0 = l0 * a0 + ls0; l1 = l1 * a1 + ls1;
        m0 = mn0; m1 = mn1;
#pragma unroll
        for (int j = 0; j < 16; j++) {
            O[j][0] *= a0; O[j][1] *= a0;
            O[j][2] *= a1; O[j][3] *= a1;
        }

        // O += P @ V via ldmatrix.trans B-fragments
#pragma unroll
        for (int t = 0; t < 4; t++) {
            uint32_t af[4] = { ph0[2 * t], ph1[2 * t], ph0[2 * t + 1], ph1[2 * t + 1] };
#pragma unroll
            for (int jp = 0; jp < 8; jp++) {
                uint32_t bf[4];
                ldm_x4_trans(bf, vbase + (((t * 16 + vrow) * VS_STR) + jp * 16 + vcol) * 2);
                mma_f16(O[jp * 2 + 0], af, bf[0], bf[1]);
                mma_f16(O[jp * 2 + 1], af, bf[2], bf[3]);
            }
        }
        __syncthreads();
    }

    {
        const float il0 = 1.f / l0, il1 = 1.f / l1;
        const int r = q0 + w * 16 + rq;
#pragma unroll
        for (int j = 0; j < 16; j++) {
            const int c = h * 128 + j * 8 + kq * 2;
            *(uint32_t*)(heads + (size_t)r * D_DIM + c) = packh2(O[j][0] * il0, O[j][1] * il0);
            *(uint32_t*)(heads + (size_t)(r + 8) * D_DIM + c) = packh2(O[j][2] * il1, O[j][3] * il1);
        }
    }
}

// ---------------------------------------------------------------------------
// LayerNorm over D=2048: fp32 in, fp16 out
// ---------------------------------------------------------------------------
__global__ void __launch_bounds__(256) layernorm_h_kernel(
    const float* __restrict__ in, const float* __restrict__ gamma,
    const float* __restrict__ beta, __half* __restrict__ out)
{
    __shared__ float red[16];
    const int row = blockIdx.x;
    const int tid = threadIdx.x;
    const float* rp = in + (size_t)row * D_DIM;

    float v[8];
    float s = 0.f, sq = 0.f;
#pragma unroll
    for (int it = 0; it < 2; ++it) {
        float4 t = *(const float4*)(rp + tid * 4 + it * 1024);
        v[it * 4 + 0] = t.x; v[it * 4 + 1] = t.y;
        v[it * 4 + 2] = t.z; v[it * 4 + 3] = t.w;
    }
#pragma unroll
    for (int i = 0; i < 8; i++) { s += v[i]; sq += v[i] * v[i]; }
#pragma unroll
    for (int o = 16; o > 0; o >>= 1) {
        s  += __shfl_xor_sync(0xffffffffu, s, o);
        sq += __shfl_xor_sync(0xffffffffu, sq, o);
    }
    if ((tid & 31) == 0) { red[tid >> 5] = s; red[8 + (tid >> 5)] = sq; }
    __syncthreads();
    if (tid < 32) {
        float ss = (tid < 8) ? red[tid] : 0.f;
        float qq = (tid < 8) ? red[8 + tid] : 0.f;
#pragma unroll
        for (int o = 4; o > 0; o >>= 1) {
            ss += __shfl_xor_sync(0xffffffffu, ss, o);
            qq += __shfl_xor_sync(0xffffffffu, qq, o);
        }
        if (tid == 0) { red[0] = ss; red[1] = qq; }
    }
    __syncthreads();
    const float mu  = red[0] * (1.f / D_DIM);
    const float var = red[1] * (1.f / D_DIM) - mu * mu;
    const float rs  = rsqrtf(var + 1e-5f);
#pragma unroll
    for (int it = 0; it < 2; ++it) {
        const int c = tid * 4 + it * 1024;
        float4 g = *(const float4*)(gamma + c);
        float4 b = *(const float4*)(beta + c);
        uint2 o;
        o.x = packh2((v[it * 4 + 0] - mu) * rs * g.x + b.x,
                     (v[it * 4 + 1] - mu) * rs * g.y + b.y);
        o.y = packh2((v[it * 4 + 2] - mu) * rs * g.z + b.z,
                     (v[it * 4 + 3] - mu) * rs * g.w + b.w);
        *(uint2*)(out + (size_t)row * D_DIM + c) = o;
    }
}

// ---------------------------------------------------------------------------
// Launch
// ---------------------------------------------------------------------------
extern "C" void kernel_launch(void* const* d_in, const int* in_sizes, int n_in,
                              void* d_out, int out_size)
{
    const float* x     = (const float*)d_in[0];
    const float* Wq    = (const float*)d_in[1];
    const float* bq    = (const float*)d_in[2];
    const float* Wk    = (const float*)d_in[3];
    const float* bk    = (const float*)d_in[4];
    const float* Wv    = (const float*)d_in[5];
    const float* bv    = (const float*)d_in[6];
    const float* Wp    = (const float*)d_in[7];
    const float* bp    = (const float*)d_in[8];
    const float* W1    = (const float*)d_in[9];
    const float* b1    = (const float*)d_in[10];
    const float* W2    = (const float*)d_in[11];
    const float* b2    = (const float*)d_in[12];
    const float* gamma = (const float*)d_in[13];
    const float* beta  = (const float*)d_in[14];
    float* out = (float*)d_out;

    __half *xh, *qkv, *heads, *ln, *h1;
    float *proj, *bqkv;
    __half *wqkvt, *wpt, *w1t, *w2t;
    cudaGetSymbolAddress((void**)&xh,    g_xh);
    cudaGetSymbolAddress((void**)&qkv,   g_qkvh);
    cudaGetSymbolAddress((void**)&heads, g_headsh);
    cudaGetSymbolAddress((void**)&proj,  g_proj);
    cudaGetSymbolAddress((void**)&ln,    g_lnh);
    cudaGetSymbolAddress((void**)&h1,    g_h1h);
    cudaGetSymbolAddress((void**)&wqkvt, g_wqkvt);
    cudaGetSymbolAddress((void**)&bqkv,  g_bqkv);
    cudaGetSymbolAddress((void**)&wpt,   g_wpt);
    cudaGetSymbolAddress((void**)&w1t,   g_w1t);
    cudaGetSymbolAddress((void**)&w2t,   g_w2t);

    // ---- prep: x->fp16, weight transposes, bias concat ----
    f2h_kernel<<<S_LEN * D_DIM / (256 * 8), 256>>>(x, xh);
    const dim3 tb(32, 8);
    transpose_qkv_kernel<<<dim3(4, 64, 48), tb>>>(Wq, Wk, Wv, wqkvt);
    transpose_h_kernel<<<dim3(64, 64, 1),  tb>>>(Wp, wpt, D_DIM, D_DIM, 0, 0);
    transpose_h_kernel<<<dim3(256, 64, 1), tb>>>(W1, w1t, D_DIM, F_DIM, 0, 0);
    transpose_h_kernel<<<dim3(64, 256, 1), tb>>>(W2, w2t, F_DIM, D_DIM, 0, 0);
    bias_concat_kernel<<<QKV_LD / 256, 256>>>(bq, bk, bv, bqkv);

    cudaFuncSetAttribute(gemm_h_kernel<0, 1>, cudaFuncAttributeMaxDynamicSharedMemorySize, GEMM_SMEM_BYTES);
    cudaFuncSetAttribute(gemm_h_kernel<1, 0>, cudaFuncAttributeMaxDynamicSharedMemorySize, GEMM_SMEM_BYTES);
    cudaFuncSetAttribute(gemm_h_kernel<2, 1>, cudaFuncAttributeMaxDynamicSharedMemorySize, GEMM_SMEM_BYTES);
    cudaFuncSetAttribute(gemm_h_kernel<0, 0>, cudaFuncAttributeMaxDynamicSharedMemorySize, GEMM_SMEM_BYTES);

    const dim3 blk(256);
    const dim3 g_qkv(QKV_LD / 128, S_LEN / 128);  // (48, 32)
    const dim3 g_dd(D_DIM / 128, S_LEN / 128);    // (16, 32)
    const dim3 g_f1(F_DIM / 128, S_LEN / 128);    // (64, 32)

    // fused QKV projection
    gemm_h_kernel<0, 1><<<g_qkv, blk, GEMM_SMEM_BYTES>>>(xh, wqkvt, bqkv, nullptr, qkv, S_LEN, QKV_LD, D_DIM);

    // flash attention
    cudaFuncSetAttribute(flash_attn_h_kernel,
                         cudaFuncAttributeMaxDynamicSharedMemorySize, FA_SMEM_BYTES);
    flash_attn_h_kernel<<<dim3(S_LEN / 128, H_NUM), blk, FA_SMEM_BYTES>>>(qkv, heads);

    // output projection + residual (fp32 x), LayerNorm
    gemm_h_kernel<1, 0><<<g_dd, blk, GEMM_SMEM_BYTES>>>(heads, wpt, bp, x, proj, S_LEN, D_DIM, D_DIM);
    layernorm_h_kernel<<<S_LEN, blk>>>(proj, gamma, beta, ln);

    // FFN
    gemm_h_kernel<2, 1><<<g_f1, blk, GEMM_SMEM_BYTES>>>(ln, w1t, b1, nullptr, h1, S_LEN, F_DIM, D_DIM);
    gemm_h_kernel<0, 0><<<g_dd, blk, GEMM_SMEM_BYTES>>>(h1, w2t, b2, nullptr, out, S_LEN, D_DIM, F_DIM);
}

// round 13
// speedup vs baseline: 1.0592x; 1.0592x over previous
#include <cuda_runtime.h>
#include <cuda_fp16.h>
#include <cstdint>

// Problem dims
#define S_LEN 4096
#define D_DIM 2048
#define H_NUM 16
#define F_DIM 8192
#define QKV_LD 6144

// ---------------------------------------------------------------------------
// Scratch (allocation is banned; use device globals)
// ---------------------------------------------------------------------------
__device__ __half g_xh[S_LEN * D_DIM];
__device__ __half g_qkvh[S_LEN * QKV_LD];
__device__ __half g_headsh[S_LEN * D_DIM];
__device__ float  g_proj[S_LEN * D_DIM];
__device__ __half g_lnh[S_LEN * D_DIM];
__device__ __half g_h1h[S_LEN * F_DIM];
// transposed fp16 weights, [N, K] row-major
__device__ __half g_wqkvt[3 * D_DIM * D_DIM];
__device__ float  g_bqkv[QKV_LD];
__device__ __half g_wpt[D_DIM * D_DIM];
__device__ __half g_w1t[F_DIM * D_DIM];
__device__ __half g_w2t[D_DIM * F_DIM];

// ---------------------------------------------------------------------------
// Portable PTX helpers (sm_80-level; tcgen05 is gated off on plain sm_103)
// ---------------------------------------------------------------------------
__device__ __forceinline__ uint32_t smem_u32(const void* p) {
    uint32_t a;
    asm("{ .reg .u64 t; cvta.to.shared.u64 t, %1; cvt.u32.u64 %0, t; }"
        : "=r"(a) : "l"(p));
    return a;
}

__device__ __forceinline__ uint32_t packh2(float a, float b) {
    __half2 h = __floats2half2_rn(a, b);
    return *reinterpret_cast<uint32_t*>(&h);
}

__device__ __forceinline__ void mma_f16(float* c, const uint32_t* a,
                                        uint32_t b0, uint32_t b1) {
    asm volatile(
        "mma.sync.aligned.m16n8k16.row.col.f32.f16.f16.f32 "
        "{%0,%1,%2,%3}, {%4,%5,%6,%7}, {%8,%9}, {%0,%1,%2,%3};"
        : "+f"(c[0]), "+f"(c[1]), "+f"(c[2]), "+f"(c[3])
        : "r"(a[0]), "r"(a[1]), "r"(a[2]), "r"(a[3]), "r"(b0), "r"(b1));
}

__device__ __forceinline__ void cp16(uint32_t saddr, const void* g) {
    asm volatile("cp.async.ca.shared.global [%0], [%1], 16;" :: "r"(saddr), "l"(g));
}
__device__ __forceinline__ void cp_commit() {
    asm volatile("cp.async.commit_group;" ::: "memory");
}
template <int N>
__device__ __forceinline__ void cp_wait() {
    asm volatile("cp.async.wait_group %0;" :: "n"(N) : "memory");
}

__device__ __forceinline__ void ldm_x4(uint32_t* r, uint32_t addr) {
    asm volatile("ldmatrix.sync.aligned.m8n8.x4.shared.b16 {%0,%1,%2,%3}, [%4];"
        : "=r"(r[0]), "=r"(r[1]), "=r"(r[2]), "=r"(r[3]) : "r"(addr));
}

__device__ __forceinline__ void ldm_x4_trans(uint32_t* r, uint32_t addr) {
    asm volatile("ldmatrix.sync.aligned.m8n8.x4.trans.shared.b16 {%0,%1,%2,%3}, [%4];"
        : "=r"(r[0]), "=r"(r[1]), "=r"(r[2]), "=r"(r[3]) : "r"(addr));
}

// ---------------------------------------------------------------------------
// fp16 warp-MMA GEMM, CTA 128x128, warp tile 32x64, BK=64, 2-stage cp.async.
// Round-9 proven configuration (2D grid, cp.async.ca).
//   EPI 0: +bias   EPI 1: +bias+res(fp32)   EPI 2: relu(+bias)
//   OH: 1 -> half output, 0 -> fp32 output
// smem row stride 72 halves (144B): ldmatrix conflict-free.
// ---------------------------------------------------------------------------
#define GSTR 72
#define STAGE_HALVES (2 * 128 * GSTR)            // A + B per stage
#define GEMM_SMEM_BYTES (2 * STAGE_HALVES * 2)   // 73728

template <int EPI, int OH>
__global__ void __launch_bounds__(256) gemm_h_kernel(
    const __half* __restrict__ A, const __half* __restrict__ Bt,
    const float* __restrict__ bias, const float* __restrict__ res,
    void* __restrict__ Cv, int M, int N, int K)
{
    extern __shared__ __half sh[];
    const uint32_t sbase = smem_u32(sh);

    float*  Cf = (float*)Cv;
    __half* Ch = (__half*)Cv;

    const int tid = threadIdx.x, lane = tid & 31, w = tid >> 5;
    const int wm = w >> 1, wn = w & 1;     // 4m x 2n; warp tile 32x64
    const int bm = blockIdx.y * 128, bn = blockIdx.x * 128;
    const int nk = K >> 6;

    const int crow = tid >> 3;        // 0..31
    const int ccol = (tid & 7) * 8;   // halves within 64-wide row

    auto load_stage = [&](int kt, int slot) {
        const int k0 = kt << 6;
        const uint32_t sa = sbase + slot * STAGE_HALVES * 2;
        const uint32_t sb = sa + 128 * GSTR * 2;
#pragma unroll
        for (int it = 0; it < 4; it++) {
            const int r = crow + it * 32;
            cp16(sa + (r * GSTR + ccol) * 2, A  + (size_t)(bm + r) * K + k0 + ccol);
            cp16(sb + (r * GSTR + ccol) * 2, Bt + (size_t)(bn + r) * K + k0 + ccol);
        }
    };

    float acc[2][8][4];
#pragma unroll
    for (int i = 0; i < 2; i++)
#pragma unroll
        for (int j = 0; j < 8; j++)
#pragma unroll
            for (int r = 0; r < 4; r++) acc[i][j][r] = 0.f;

    load_stage(0, 0); cp_commit();

    const int frow = lane & 15;
    const int fcol = (lane >> 4) * 8;

    for (int kt = 0; kt < nk; kt++) {
        cp_wait<0>();
        __syncthreads();
        if (kt + 1 < nk) { load_stage(kt + 1, (kt + 1) & 1); cp_commit(); }

        const uint32_t sa = sbase + (kt & 1) * STAGE_HALVES * 2;
        const uint32_t sb = sa + 128 * GSTR * 2;

#pragma unroll
        for (int kk = 0; kk < 4; kk++) {
            uint32_t af[2][4], bf[4][4];
#pragma unroll
            for (int i = 0; i < 2; i++)
                ldm_x4(af[i], sa + ((wm * 32 + i * 16 + frow) * GSTR + kk * 16 + fcol) * 2);
#pragma unroll
            for (int j2 = 0; j2 < 4; j2++)
                ldm_x4(bf[j2], sb + ((wn * 64 + j2 * 16 + frow) * GSTR + kk * 16 + fcol) * 2);
#pragma unroll
            for (int i = 0; i < 2; i++)
#pragma unroll
                for (int j = 0; j < 8; j++)
                    mma_f16(acc[i][j], af[i], bf[j >> 1][j & 1], bf[j >> 1][2 + (j & 1)]);
        }
    }

    // epilogue
#pragma unroll
    for (int i = 0; i < 2; i++) {
#pragma unroll
        for (int j = 0; j < 8; j++) {
            const int row = bm + wm * 32 + i * 16 + (lane >> 2);
            const int col = bn + wn * 64 + j * 8 + (lane & 3) * 2;
            const float2 bv = *(const float2*)(bias + col);
#pragma unroll
            for (int hf = 0; hf < 2; hf++) {
                const int r = row + hf * 8;
                float vx = acc[i][j][hf * 2 + 0] + bv.x;
                float vy = acc[i][j][hf * 2 + 1] + bv.y;
                if (EPI == 1) {
                    float2 rv = *(const float2*)(res + (size_t)r * N + col);
                    vx += rv.x; vy += rv.y;
                }
                if (EPI == 2) { vx = fmaxf(vx, 0.f); vy = fmaxf(vy, 0.f); }
                if (OH) {
                    *(uint32_t*)(Ch + (size_t)r * N + col) = packh2(vx, vy);
                } else {
                    float2 o = { vx, vy };
                    *(float2*)(Cf + (size_t)r * N + col) = o;
                }
            }
        }
    }
}

// ---------------------------------------------------------------------------
// fp32 -> fp16 bulk convert
// ---------------------------------------------------------------------------
__global__ void __launch_bounds__(256) f2h_kernel(
    const float* __restrict__ in, __half* __restrict__ out)
{
    const size_t i = ((size_t)blockIdx.x * 256 + threadIdx.x) * 8;
    float4 a = *(const float4*)(in + i);
    float4 b = *(const float4*)(in + i + 4);
    uint4 o;
    o.x = packh2(a.x, a.y); o.y = packh2(a.z, a.w);
    o.z = packh2(b.x, b.y); o.w = packh2(b.z, b.w);
    *(uint4*)(out + i) = o;
}

// bias concat for fused QKV
__global__ void bias_concat_kernel(const float* __restrict__ bq,
                                   const float* __restrict__ bk,
                                   const float* __restrict__ bv,
                                   float* __restrict__ out)
{
    const int i = blockIdx.x * 256 + threadIdx.x;
    float v = (i < 2048) ? bq[i] : (i < 4096) ? bk[i - 2048] : bv[i - 4096];
    out[i] = v;
}

// ---------------------------------------------------------------------------
// Fused QKV weight transpose: [H,D,128] x3 -> stacked fp16 [6144, 2048].
// 64x64 tiles, __half2 stores (128B per warp-row).
// ---------------------------------------------------------------------------
__global__ void __launch_bounds__(256) transpose_qkv_kernel(
    const float* __restrict__ Wq, const float* __restrict__ Wk,
    const float* __restrict__ Wv, __half* __restrict__ out)
{
    __shared__ float t[64][65];
    const int z = blockIdx.z, which = z >> 4, hh = z & 15;
    const float* in = (which == 0) ? Wq : (which == 1) ? Wk : Wv;
    in  += (size_t)hh * D_DIM * 128;
    out += (size_t)which * D_DIM * D_DIM + (size_t)hh * 128 * D_DIM;
    const int k0 = blockIdx.y * 64;
    const int n0 = blockIdx.x * 64;
    const int tx = threadIdx.x, ty = threadIdx.y;
#pragma unroll
    for (int i = 0; i < 64; i += 8) {
        t[ty + i][tx]      = in[(size_t)(k0 + ty + i) * 128 + n0 + tx];
        t[ty + i][tx + 32] = in[(size_t)(k0 + ty + i) * 128 + n0 + tx + 32];
    }
    __syncthreads();
#pragma unroll
    for (int i = 0; i < 64; i += 8) {
        const int n = n0 + ty + i;
        __half2 v = __floats2half2_rn(t[2 * tx][ty + i], t[2 * tx + 1][ty + i]);
        *(__half2*)(out + (size_t)n * D_DIM + k0 + 2 * tx) = v;
    }
}

// ---------------------------------------------------------------------------
// Transpose fp32 [K,N] -> fp16 [N,K]. 64x64 tiles, __half2 stores.
// ---------------------------------------------------------------------------
__global__ void __launch_bounds__(256) transpose_h_kernel(
    const float* __restrict__ in, __half* __restrict__ out, int K, int N)
{
    __shared__ float t[64][65];
    const int k0 = blockIdx.y * 64;
    const int n0 = blockIdx.x * 64;
    const int tx = threadIdx.x, ty = threadIdx.y;
#pragma unroll
    for (int i = 0; i < 64; i += 8) {
        t[ty + i][tx]      = in[(size_t)(k0 + ty + i) * N + n0 + tx];
        t[ty + i][tx + 32] = in[(size_t)(k0 + ty + i) * N + n0 + tx + 32];
    }
    __syncthreads();
#pragma unroll
    for (int i = 0; i < 64; i += 8) {
        const int n = n0 + ty + i;
        __half2 v = __floats2half2_rn(t[2 * tx][ty + i], t[2 * tx + 1][ty + i]);
        *(__half2*)(out + (size_t)n * K + k0 + 2 * tx) = v;
    }
}

// ---------------------------------------------------------------------------
// Flash attention, fp16 mma, FA2-style (round-9 base).
// NEW: QK K-fragments via ldmatrix.x4 (was 128 scalar LDS.32 per warp-tile).
// KS_STR=136 halves = 272B; 272 mod 128 = 16 -> 8-row ldm addresses distinct.
// V row-major; PV B-fragments via ldmatrix.x4.trans. Single-buffer K/V.
// ---------------------------------------------------------------------------
#define QS_STR 136
#define KS_STR 136
#define VS_STR 136
#define FA_SMEM_BYTES ((128 * QS_STR + 64 * KS_STR + 64 * VS_STR) * 2)  // 69632

__global__ void __launch_bounds__(256) flash_attn_h_kernel(
    const __half* __restrict__ qkv, __half* __restrict__ heads)
{
    extern __shared__ __half smh[];
    __half* Qs  = smh;
    __half* Ks  = Qs + 128 * QS_STR;
    __half* Vs  = Ks + 64 * KS_STR;
    const uint32_t* Qs32 = (const uint32_t*)Qs;
    const uint32_t kbase = smem_u32(Ks);
    const uint32_t vbase = smem_u32(Vs);

    const __half* qb = qkv;
    const __half* kb = qkv + 2048;
    const __half* vb = qkv + 4096;

    const int h   = blockIdx.y;
    const int q0  = blockIdx.x * 128;
    const int tid = threadIdx.x, lane = tid & 31, w = tid >> 5;
    const int rq = lane >> 2, kq = lane & 3;
    const int frow = lane & 15;
    const int fcol = (lane >> 4) * 8;
    const float scale = 0.08838834764831845f;

    {
        int idx = tid * 8;
#pragma unroll
        for (int it = 0; it < 8; it++) {
            int r = idx >> 7, c = idx & 127;
            *(uint4*)(Qs + r * QS_STR + c) =
                *(const uint4*)(qb + (size_t)(q0 + r) * QKV_LD + h * 128 + c);
            idx += 2048;
        }
    }
    __syncthreads();

    uint32_t qf[8][4];
    {
        const int r = w * 16 + rq;
#pragma unroll
        for (int ks = 0; ks < 8; ks++) {
            qf[ks][0] = Qs32[r * 68 + ks * 8 + kq];
            qf[ks][1] = Qs32[(r + 8) * 68 + ks * 8 + kq];
            qf[ks][2] = Qs32[r * 68 + ks * 8 + 4 + kq];
            qf[ks][3] = Qs32[(r + 8) * 68 + ks * 8 + 4 + kq];
        }
    }

    float O[16][4];
#pragma unroll
    for (int j = 0; j < 16; j++)
#pragma unroll
        for (int r = 0; r < 4; r++) O[j][r] = 0.f;
    float m0 = -1e30f, m1 = -1e30f, l0 = 0.f, l1 = 0.f;

    const uint32_t vrow = lane & 15;
    const uint32_t vcol = (lane >> 4) * 8;

    for (int kblk = 0; kblk < 64; kblk++) {
        {
            int idx = tid * 8;
#pragma unroll
            for (int it = 0; it < 4; it++) {
                int r = idx >> 7, c = idx & 127;
                *(uint4*)(Ks + r * KS_STR + c) =
                    *(const uint4*)(kb + (size_t)(kblk * 64 + r) * QKV_LD + h * 128 + c);
                *(uint4*)(Vs + r * VS_STR + c) =
                    *(const uint4*)(vb + (size_t)(kblk * 64 + r) * QKV_LD + h * 128 + c);
                idx += 2048;
            }
        }
        __syncthreads();

        // S = Q @ K^T; K-fragments via ldmatrix (same mapping as GEMM B)
        float facc[8][4];
#pragma unroll
        for (int j = 0; j < 8; j++)
#pragma unroll
            for (int r = 0; r < 4; r++) facc[j][r] = 0.f;
#pragma unroll
        for (int ks = 0; ks < 8; ks++) {
            uint32_t bf[4][4];
#pragma unroll
            for (int j2 = 0; j2 < 4; j2++)
                ldm_x4(bf[j2], kbase + ((j2 * 16 + frow) * KS_STR + ks * 16 + fcol) * 2);
#pragma unroll
            for (int j = 0; j < 8; j++)
                mma_f16(facc[j], qf[ks], bf[j >> 1][j & 1], bf[j >> 1][2 + (j & 1)]);
        }

        float mx0 = -1e30f, mx1 = -1e30f;
#pragma unroll
        for (int j = 0; j < 8; j++) {
            facc[j][0] *= scale; facc[j][1] *= scale;
            facc[j][2] *= scale; facc[j][3] *= scale;
            mx0 = fmaxf(mx0, fmaxf(facc[j][0], facc[j][1]));
            mx1 = fmaxf(mx1, fmaxf(facc[j][2], facc[j][3]));
        }
        mx0 = fmaxf(mx0, __shfl_xor_sync(0xffffffffu, mx0, 1));
        mx0 = fmaxf(mx0, __shfl_xor_sync(0xffffffffu, mx0, 2));
        mx1 = fmaxf(mx1, __shfl_xor_sync(0xffffffffu, mx1, 1));
        mx1 = fmaxf(mx1, __shfl_xor_sync(0xffffffffu, mx1, 2));
        const float mn0 = fmaxf(m0, mx0), mn1 = fmaxf(m1, mx1);

        uint32_t ph0[8], ph1[8];
        float ls0 = 0.f, ls1 = 0.f;
#pragma unroll
        for (int j = 0; j < 8; j++) {
            float p0 = __expf(facc[j][0] - mn0);
            float p1 = __expf(facc[j][1] - mn0);
            float p2 = __expf(facc[j][2] - mn1);
            float p3 = __expf(facc[j][3] - mn1);
            ph0[j] = packh2(p0, p1);
            ph1[j] = packh2(p2, p3);
            ls0 += p0 + p1; ls1 += p2 + p3;
        }
        ls0 += __shfl_xor_sync(0xffffffffu, ls0, 1);
        ls0 += __shfl_xor_sync(0xffffffffu, ls0, 2);
        ls1 += __shfl_xor_sync(0xffffffffu, ls1, 1);
        ls1 += __shfl_xor_sync(0xffffffffu, ls1, 2);

        const float a0 = __expf(m0 - mn0), a1 = __expf(m1 - mn1);
        l0 = l0 * a0 + ls0; l1 = l1 * a1 + ls1;
        m0 = mn0; m1 = mn1;
#pragma unroll
        for (int j = 0; j < 16; j++) {
            O[j][0] *= a0; O[j][1] *= a0;
            O[j][2] *= a1; O[j][3] *= a1;
        }

        // O += P @ V via ldmatrix.trans B-fragments
#pragma unroll
        for (int t = 0; t < 4; t++) {
            uint32_t af[4] = { ph0[2 * t], ph1[2 * t], ph0[2 * t + 1], ph1[2 * t + 1] };
#pragma unroll
            for (int jp = 0; jp < 8; jp++) {
                uint32_t bf[4];
                ldm_x4_trans(bf, vbase + (((t * 16 + vrow) * VS_STR) + jp * 16 + vcol) * 2);
                mma_f16(O[jp * 2 + 0], af, bf[0], bf[1]);
                mma_f16(O[jp * 2 + 1], af, bf[2], bf[3]);
            }
        }
        __syncthreads();
    }

    {
        const float il0 = 1.f / l0, il1 = 1.f / l1;
        const int r = q0 + w * 16 + rq;
#pragma unroll
        for (int j = 0; j < 16; j++) {
            const int c = h * 128 + j * 8 + kq * 2;
            *(uint32_t*)(heads + (size_t)r * D_DIM + c) = packh2(O[j][0] * il0, O[j][1] * il0);
            *(uint32_t*)(heads + (size_t)(r + 8) * D_DIM + c) = packh2(O[j][2] * il1, O[j][3] * il1);
        }
    }
}

// ---------------------------------------------------------------------------
// LayerNorm over D=2048: fp32 in, fp16 out
// ---------------------------------------------------------------------------
__global__ void __launch_bounds__(256) layernorm_h_kernel(
    const float* __restrict__ in, const float* __restrict__ gamma,
    const float* __restrict__ beta, __half* __restrict__ out)
{
    __shared__ float red[16];
    const int row = blockIdx.x;
    const int tid = threadIdx.x;
    const float* rp = in + (size_t)row * D_DIM;

    float v[8];
    float s = 0.f, sq = 0.f;
#pragma unroll
    for (int it = 0; it < 2; ++it) {
        float4 t = *(const float4*)(rp + tid * 4 + it * 1024);
        v[it * 4 + 0] = t.x; v[it * 4 + 1] = t.y;
        v[it * 4 + 2] = t.z; v[it * 4 + 3] = t.w;
    }
#pragma unroll
    for (int i = 0; i < 8; i++) { s += v[i]; sq += v[i] * v[i]; }
#pragma unroll
    for (int o = 16; o > 0; o >>= 1) {
        s  += __shfl_xor_sync(0xffffffffu, s, o);
        sq += __shfl_xor_sync(0xffffffffu, sq, o);
    }
    if ((tid & 31) == 0) { red[tid >> 5] = s; red[8 + (tid >> 5)] = sq; }
    __syncthreads();
    if (tid < 32) {
        float ss = (tid < 8) ? red[tid] : 0.f;
        float qq = (tid < 8) ? red[8 + tid] : 0.f;
#pragma unroll
        for (int o = 4; o > 0; o >>= 1) {
            ss += __shfl_xor_sync(0xffffffffu, ss, o);
            qq += __shfl_xor_sync(0xffffffffu, qq, o);
        }
        if (tid == 0) { red[0] = ss; red[1] = qq; }
    }
    __syncthreads();
    const float mu  = red[0] * (1.f / D_DIM);
    const float var = red[1] * (1.f / D_DIM) - mu * mu;
    const float rs  = rsqrtf(var + 1e-5f);
#pragma unroll
    for (int it = 0; it < 2; ++it) {
        const int c = tid * 4 + it * 1024;
        float4 g = *(const float4*)(gamma + c);
        float4 b = *(const float4*)(beta + c);
        uint2 o;
        o.x = packh2((v[it * 4 + 0] - mu) * rs * g.x + b.x,
                     (v[it * 4 + 1] - mu) * rs * g.y + b.y);
        o.y = packh2((v[it * 4 + 2] - mu) * rs * g.z + b.z,
                     (v[it * 4 + 3] - mu) * rs * g.w + b.w);
        *(uint2*)(out + (size_t)row * D_DIM + c) = o;
    }
}

// ---------------------------------------------------------------------------
// Launch
// ---------------------------------------------------------------------------
extern "C" void kernel_launch(void* const* d_in, const int* in_sizes, int n_in,
                              void* d_out, int out_size)
{
    const float* x     = (const float*)d_in[0];
    const float* Wq    = (const float*)d_in[1];
    const float* bq    = (const float*)d_in[2];
    const float* Wk    = (const float*)d_in[3];
    const float* bk    = (const float*)d_in[4];
    const float* Wv    = (const float*)d_in[5];
    const float* bv    = (const float*)d_in[6];
    const float* Wp    = (const float*)d_in[7];
    const float* bp    = (const float*)d_in[8];
    const float* W1    = (const float*)d_in[9];
    const float* b1    = (const float*)d_in[10];
    const float* W2    = (const float*)d_in[11];
    const float* b2    = (const float*)d_in[12];
    const float* gamma = (const float*)d_in[13];
    const float* beta  = (const float*)d_in[14];
    float* out = (float*)d_out;

    __half *xh, *qkv, *heads, *ln, *h1;
    float *proj, *bqkv;
    __half *wqkvt, *wpt, *w1t, *w2t;
    cudaGetSymbolAddress((void**)&xh,    g_xh);
    cudaGetSymbolAddress((void**)&qkv,   g_qkvh);
    cudaGetSymbolAddress((void**)&heads, g_headsh);
    cudaGetSymbolAddress((void**)&proj,  g_proj);
    cudaGetSymbolAddress((void**)&ln,    g_lnh);
    cudaGetSymbolAddress((void**)&h1,    g_h1h);
    cudaGetSymbolAddress((void**)&wqkvt, g_wqkvt);
    cudaGetSymbolAddress((void**)&bqkv,  g_bqkv);
    cudaGetSymbolAddress((void**)&wpt,   g_wpt);
    cudaGetSymbolAddress((void**)&w1t,   g_w1t);
    cudaGetSymbolAddress((void**)&w2t,   g_w2t);

    // ---- prep: x->fp16, weight transposes, bias concat ----
    f2h_kernel<<<S_LEN * D_DIM / (256 * 8), 256>>>(x, xh);
    const dim3 tb(32, 8);
    transpose_qkv_kernel<<<dim3(2, 32, 48), tb>>>(Wq, Wk, Wv, wqkvt);
    transpose_h_kernel<<<dim3(32, 32, 1),  tb>>>(Wp, wpt, D_DIM, D_DIM);
    transpose_h_kernel<<<dim3(128, 32, 1), tb>>>(W1, w1t, D_DIM, F_DIM);
    transpose_h_kernel<<<dim3(32, 128, 1), tb>>>(W2, w2t, F_DIM, D_DIM);
    bias_concat_kernel<<<QKV_LD / 256, 256>>>(bq, bk, bv, bqkv);

    cudaFuncSetAttribute(gemm_h_kernel<0, 1>, cudaFuncAttributeMaxDynamicSharedMemorySize, GEMM_SMEM_BYTES);
    cudaFuncSetAttribute(gemm_h_kernel<1, 0>, cudaFuncAttributeMaxDynamicSharedMemorySize, GEMM_SMEM_BYTES);
    cudaFuncSetAttribute(gemm_h_kernel<2, 1>, cudaFuncAttributeMaxDynamicSharedMemorySize, GEMM_SMEM_BYTES);
    cudaFuncSetAttribute(gemm_h_kernel<0, 0>, cudaFuncAttributeMaxDynamicSharedMemorySize, GEMM_SMEM_BYTES);

    const dim3 blk(256);
    const dim3 g_qkv(QKV_LD / 128, S_LEN / 128);  // (48, 32)
    const dim3 g_dd(D_DIM / 128, S_LEN / 128);    // (16, 32)
    const dim3 g_f1(F_DIM / 128, S_LEN / 128);    // (64, 32)

    // fused QKV projection
    gemm_h_kernel<0, 1><<<g_qkv, blk, GEMM_SMEM_BYTES>>>(xh, wqkvt, bqkv, nullptr, qkv, S_LEN, QKV_LD, D_DIM);

    // flash attention
    cudaFuncSetAttribute(flash_attn_h_kernel,
                         cudaFuncAttributeMaxDynamicSharedMemorySize, FA_SMEM_BYTES);
    flash_attn_h_kernel<<<dim3(S_LEN / 128, H_NUM), blk, FA_SMEM_BYTES>>>(qkv, heads);

    // output projection + residual (fp32 x), LayerNorm
    gemm_h_kernel<1, 0><<<g_dd, blk, GEMM_SMEM_BYTES>>>(heads, wpt, bp, x, proj, S_LEN, D_DIM, D_DIM);
    layernorm_h_kernel<<<S_LEN, blk>>>(proj, gamma, beta, ln);

    // FFN
    gemm_h_kernel<2, 1><<<g_f1, blk, GEMM_SMEM_BYTES>>>(ln, w1t, b1, nullptr, h1, S_LEN, F_DIM, D_DIM);
    gemm_h_kernel<0, 0><<<g_dd, blk, GEMM_SMEM_BYTES>>>(h1, w2t, b2, nullptr, out, S_LEN, D_DIM, F_DIM);
}

// round 14
// speedup vs baseline: 1.0770x; 1.0168x over previous
#include <cuda_runtime.h>
#include <cuda_fp16.h>
#include <cstdint>

// Problem dims
#define S_LEN 4096
#define D_DIM 2048
#define H_NUM 16
#define F_DIM 8192
#define QKV_LD 6144

// ---------------------------------------------------------------------------
// Scratch (allocation is banned; use device globals)
// ---------------------------------------------------------------------------
__device__ __half g_xh[S_LEN * D_DIM];
__device__ __half g_qkvh[S_LEN * QKV_LD];
__device__ __half g_headsh[S_LEN * D_DIM];
__device__ float  g_proj[S_LEN * D_DIM];
__device__ __half g_lnh[S_LEN * D_DIM];
__device__ __half g_h1h[S_LEN * F_DIM];
// transposed fp16 weights, [N, K] row-major
__device__ __half g_wqkvt[3 * D_DIM * D_DIM];
__device__ float  g_bqkv[QKV_LD];
__device__ __half g_wpt[D_DIM * D_DIM];
__device__ __half g_w1t[F_DIM * D_DIM];
__device__ __half g_w2t[D_DIM * F_DIM];

// ---------------------------------------------------------------------------
// Portable PTX helpers (sm_80-level; tcgen05 is gated off on plain sm_103)
// ---------------------------------------------------------------------------
__device__ __forceinline__ uint32_t smem_u32(const void* p) {
    uint32_t a;
    asm("{ .reg .u64 t; cvta.to.shared.u64 t, %1; cvt.u32.u64 %0, t; }"
        : "=r"(a) : "l"(p));
    return a;
}

__device__ __forceinline__ uint32_t packh2(float a, float b) {
    __half2 h = __floats2half2_rn(a, b);
    return *reinterpret_cast<uint32_t*>(&h);
}

__device__ __forceinline__ void mma_f16(float* c, const uint32_t* a,
                                        uint32_t b0, uint32_t b1) {
    asm volatile(
        "mma.sync.aligned.m16n8k16.row.col.f32.f16.f16.f32 "
        "{%0,%1,%2,%3}, {%4,%5,%6,%7}, {%8,%9}, {%0,%1,%2,%3};"
        : "+f"(c[0]), "+f"(c[1]), "+f"(c[2]), "+f"(c[3])
        : "r"(a[0]), "r"(a[1]), "r"(a[2]), "r"(a[3]), "r"(b0), "r"(b1));
}

__device__ __forceinline__ void cp16(uint32_t saddr, const void* g) {
    asm volatile("cp.async.ca.shared.global [%0], [%1], 16;" :: "r"(saddr), "l"(g));
}
__device__ __forceinline__ void cp_commit() {
    asm volatile("cp.async.commit_group;" ::: "memory");
}
template <int N>
__device__ __forceinline__ void cp_wait() {
    asm volatile("cp.async.wait_group %0;" :: "n"(N) : "memory");
}

__device__ __forceinline__ void ldm_x4(uint32_t* r, uint32_t addr) {
    asm volatile("ldmatrix.sync.aligned.m8n8.x4.shared.b16 {%0,%1,%2,%3}, [%4];"
        : "=r"(r[0]), "=r"(r[1]), "=r"(r[2]), "=r"(r[3]) : "r"(addr));
}

__device__ __forceinline__ void ldm_x4_trans(uint32_t* r, uint32_t addr) {
    asm volatile("ldmatrix.sync.aligned.m8n8.x4.trans.shared.b16 {%0,%1,%2,%3}, [%4];"
        : "=r"(r[0]), "=r"(r[1]), "=r"(r[2]), "=r"(r[3]) : "r"(addr));
}

// ---------------------------------------------------------------------------
// fp16 warp-MMA GEMM, CTA 128x128, warp tile 32x64, BK=64, 2-stage cp.async.
// Round-9 proven configuration (2D grid, cp.async.ca).
//   EPI 0: +bias   EPI 1: +bias+res(fp32)   EPI 2: relu(+bias)
//   OH: 1 -> half output, 0 -> fp32 output
// smem row stride 72 halves (144B): ldmatrix conflict-free.
// ---------------------------------------------------------------------------
#define GSTR 72
#define STAGE_HALVES (2 * 128 * GSTR)            // A + B per stage
#define GEMM_SMEM_BYTES (2 * STAGE_HALVES * 2)   // 73728

template <int EPI, int OH>
__global__ void __launch_bounds__(256) gemm_h_kernel(
    const __half* __restrict__ A, const __half* __restrict__ Bt,
    const float* __restrict__ bias, const float* __restrict__ res,
    void* __restrict__ Cv, int M, int N, int K)
{
    extern __shared__ __half sh[];
    const uint32_t sbase = smem_u32(sh);

    float*  Cf = (float*)Cv;
    __half* Ch = (__half*)Cv;

    const int tid = threadIdx.x, lane = tid & 31, w = tid >> 5;
    const int wm = w >> 1, wn = w & 1;     // 4m x 2n; warp tile 32x64
    const int bm = blockIdx.y * 128, bn = blockIdx.x * 128;
    const int nk = K >> 6;

    const int crow = tid >> 3;        // 0..31
    const int ccol = (tid & 7) * 8;   // halves within 64-wide row

    auto load_stage = [&](int kt, int slot) {
        const int k0 = kt << 6;
        const uint32_t sa = sbase + slot * STAGE_HALVES * 2;
        const uint32_t sb = sa + 128 * GSTR * 2;
#pragma unroll
        for (int it = 0; it < 4; it++) {
            const int r = crow + it * 32;
            cp16(sa + (r * GSTR + ccol) * 2, A  + (size_t)(bm + r) * K + k0 + ccol);
            cp16(sb + (r * GSTR + ccol) * 2, Bt + (size_t)(bn + r) * K + k0 + ccol);
        }
    };

    float acc[2][8][4];
#pragma unroll
    for (int i = 0; i < 2; i++)
#pragma unroll
        for (int j = 0; j < 8; j++)
#pragma unroll
            for (int r = 0; r < 4; r++) acc[i][j][r] = 0.f;

    load_stage(0, 0); cp_commit();

    const int frow = lane & 15;
    const int fcol = (lane >> 4) * 8;

    for (int kt = 0; kt < nk; kt++) {
        cp_wait<0>();
        __syncthreads();
        if (kt + 1 < nk) { load_stage(kt + 1, (kt + 1) & 1); cp_commit(); }

        const uint32_t sa = sbase + (kt & 1) * STAGE_HALVES * 2;
        const uint32_t sb = sa + 128 * GSTR * 2;

#pragma unroll
        for (int kk = 0; kk < 4; kk++) {
            uint32_t af[2][4], bf[4][4];
#pragma unroll
            for (int i = 0; i < 2; i++)
                ldm_x4(af[i], sa + ((wm * 32 + i * 16 + frow) * GSTR + kk * 16 + fcol) * 2);
#pragma unroll
            for (int j2 = 0; j2 < 4; j2++)
                ldm_x4(bf[j2], sb + ((wn * 64 + j2 * 16 + frow) * GSTR + kk * 16 + fcol) * 2);
#pragma unroll
            for (int i = 0; i < 2; i++)
#pragma unroll
                for (int j = 0; j < 8; j++)
                    mma_f16(acc[i][j], af[i], bf[j >> 1][j & 1], bf[j >> 1][2 + (j & 1)]);
        }
    }

    // epilogue
#pragma unroll
    for (int i = 0; i < 2; i++) {
#pragma unroll
        for (int j = 0; j < 8; j++) {
            const int row = bm + wm * 32 + i * 16 + (lane >> 2);
            const int col = bn + wn * 64 + j * 8 + (lane & 3) * 2;
            const float2 bv = *(const float2*)(bias + col);
#pragma unroll
            for (int hf = 0; hf < 2; hf++) {
                const int r = row + hf * 8;
                float vx = acc[i][j][hf * 2 + 0] + bv.x;
                float vy = acc[i][j][hf * 2 + 1] + bv.y;
                if (EPI == 1) {
                    float2 rv = *(const float2*)(res + (size_t)r * N + col);
                    vx += rv.x; vy += rv.y;
                }
                if (EPI == 2) { vx = fmaxf(vx, 0.f); vy = fmaxf(vy, 0.f); }
                if (OH) {
                    *(uint32_t*)(Ch + (size_t)r * N + col) = packh2(vx, vy);
                } else {
                    float2 o = { vx, vy };
                    *(float2*)(Cf + (size_t)r * N + col) = o;
                }
            }
        }
    }
}

// ---------------------------------------------------------------------------
// fp32 -> fp16 bulk convert (x)
// ---------------------------------------------------------------------------
__global__ void __launch_bounds__(256) f2h_kernel(
    const float* __restrict__ in, __half* __restrict__ out)
{
    const size_t i = ((size_t)blockIdx.x * 256 + threadIdx.x) * 8;
    float4 a = *(const float4*)(in + i);
    float4 b = *(const float4*)(in + i + 4);
    uint4 o;
    o.x = packh2(a.x, a.y); o.y = packh2(a.z, a.w);
    o.z = packh2(b.x, b.y); o.w = packh2(b.z, b.w);
    *(uint4*)(out + i) = o;
}

// ---------------------------------------------------------------------------
// Unified weight prep: ALL transposes + bias concat in ONE launch.
// 64x64 transpose tiles, flattened 1D tile index:
//   [0, 3072)        : QKV   (48 z-slices x (2 x 32) tiles)   -> g_wqkvt
//   [3072, 4096)     : Wp    (32 x 32 tiles)                  -> g_wpt
//   [4096, 8192)     : W1    (128 x 32 tiles)  [K=2048,N=8192]-> g_w1t
//   [8192, 12288)    : W2    (32 x 128 tiles)  [K=8192,N=2048]-> g_w2t
//   [12288, 12312)   : bias concat (24 blocks x 256)
// block (32, 8).
// ---------------------------------------------------------------------------
__global__ void __launch_bounds__(256) prep_weights_kernel(
    const float* __restrict__ Wq, const float* __restrict__ Wk,
    const float* __restrict__ Wv, const float* __restrict__ Wp,
    const float* __restrict__ W1, const float* __restrict__ W2,
    const float* __restrict__ bq, const float* __restrict__ bk,
    const float* __restrict__ bv,
    __half* __restrict__ wqkvt, __half* __restrict__ wpt,
    __half* __restrict__ w1t,   __half* __restrict__ w2t,
    float* __restrict__ bqkv)
{
    const int bid = blockIdx.x;
    const int tid = threadIdx.y * 32 + threadIdx.x;

    if (bid >= 12288) {  // bias concat
        const int i = (bid - 12288) * 256 + tid;
        float v = (i < 2048) ? bq[i] : (i < 4096) ? bk[i - 2048] : bv[i - 4096];
        bqkv[i] = v;
        return;
    }

    const float* in;
    __half* out;
    int K, N, k0, n0;
    if (bid < 3072) {            // QKV: z = bid/64, tile = bid%64 over (2 x 32)
        const int z = bid >> 6, t = bid & 63;
        const int which = z >> 4, hh = z & 15;
        in  = ((which == 0) ? Wq : (which == 1) ? Wk : Wv) + (size_t)hh * D_DIM * 128;
        out = wqkvt + (size_t)which * D_DIM * D_DIM + (size_t)hh * 128 * D_DIM;
        K = D_DIM; N = 128;
        n0 = (t & 1) * 64; k0 = (t >> 1) * 64;
    } else if (bid < 4096) {     // Wp (32 x 32)
        const int t = bid - 3072;
        in = Wp; out = wpt; K = D_DIM; N = D_DIM;
        n0 = (t & 31) * 64; k0 = (t >> 5) * 64;
    } else if (bid < 8192) {     // W1 (128 x 32)
        const int t = bid - 4096;
        in = W1; out = w1t; K = D_DIM; N = F_DIM;
        n0 = (t & 127) * 64; k0 = (t >> 7) * 64;
    } else {                     // W2 (32 x 128)
        const int t = bid - 8192;
        in = W2; out = w2t; K = F_DIM; N = D_DIM;
        n0 = (t & 31) * 64; k0 = (t >> 5) * 64;
    }

    __shared__ float t[64][65];
    const int tx = threadIdx.x, ty = threadIdx.y;
#pragma unroll
    for (int i = 0; i < 64; i += 8) {
        t[ty + i][tx]      = in[(size_t)(k0 + ty + i) * N + n0 + tx];
        t[ty + i][tx + 32] = in[(size_t)(k0 + ty + i) * N + n0 + tx + 32];
    }
    __syncthreads();
#pragma unroll
    for (int i = 0; i < 64; i += 8) {
        const int n = n0 + ty + i;
        __half2 v = __floats2half2_rn(t[2 * tx][ty + i], t[2 * tx + 1][ty + i]);
        *(__half2*)(out + (size_t)n * K + k0 + 2 * tx) = v;
    }
}

// ---------------------------------------------------------------------------
// Flash attention, fp16 mma, FA2-style (round-13 base).
// exp2f with folded scale*log2e constant (drops hidden log2e FMUL in __expf).
// ---------------------------------------------------------------------------
#define QS_STR 136
#define KS_STR 136
#define VS_STR 136
#define FA_SMEM_BYTES ((128 * QS_STR + 64 * KS_STR + 64 * VS_STR) * 2)  // 69632

__global__ void __launch_bounds__(256) flash_attn_h_kernel(
    const __half* __restrict__ qkv, __half* __restrict__ heads)
{
    extern __shared__ __half smh[];
    __half* Qs  = smh;
    __half* Ks  = Qs + 128 * QS_STR;
    __half* Vs  = Ks + 64 * KS_STR;
    const uint32_t* Qs32 = (const uint32_t*)Qs;
    const uint32_t kbase = smem_u32(Ks);
    const uint32_t vbase = smem_u32(Vs);

    const __half* qb = qkv;
    const __half* kb = qkv + 2048;
    const __half* vb = qkv + 4096;

    const int h   = blockIdx.y;
    const int q0  = blockIdx.x * 128;
    const int tid = threadIdx.x, lane = tid & 31, w = tid >> 5;
    const int rq = lane >> 2, kq = lane & 3;
    const int frow = lane & 15;
    const int fcol = (lane >> 4) * 8;
    // scale * log2(e): softmax computed in base-2 domain
    const float scl2 = 0.08838834764831845f * 1.4426950408889634f;

    {
        int idx = tid * 8;
#pragma unroll
        for (int it = 0; it < 8; it++) {
            int r = idx >> 7, c = idx & 127;
            *(uint4*)(Qs + r * QS_STR + c) =
                *(const uint4*)(qb + (size_t)(q0 + r) * QKV_LD + h * 128 + c);
            idx += 2048;
        }
    }
    __syncthreads();

    uint32_t qf[8][4];
    {
        const int r = w * 16 + rq;
#pragma unroll
        for (int ks = 0; ks < 8; ks++) {
            qf[ks][0] = Qs32[r * 68 + ks * 8 + kq];
            qf[ks][1] = Qs32[(r + 8) * 68 + ks * 8 + kq];
            qf[ks][2] = Qs32[r * 68 + ks * 8 + 4 + kq];
            qf[ks][3] = Qs32[(r + 8) * 68 + ks * 8 + 4 + kq];
        }
    }

    float O[16][4];
#pragma unroll
    for (int j = 0; j < 16; j++)
#pragma unroll
        for (int r = 0; r < 4; r++) O[j][r] = 0.f;
    float m0 = -1e30f, m1 = -1e30f, l0 = 0.f, l1 = 0.f;

    const uint32_t vrow = lane & 15;
    const uint32_t vcol = (lane >> 4) * 8;

    for (int kblk = 0; kblk < 64; kblk++) {
        {
            int idx = tid * 8;
#pragma unroll
            for (int it = 0; it < 4; it++) {
                int r = idx >> 7, c = idx & 127;
                *(uint4*)(Ks + r * KS_STR + c) =
                    *(const uint4*)(kb + (size_t)(kblk * 64 + r) * QKV_LD + h * 128 + c);
                *(uint4*)(Vs + r * VS_STR + c) =
                    *(const uint4*)(vb + (size_t)(kblk * 64 + r) * QKV_LD + h * 128 + c);
                idx += 2048;
            }
        }
        __syncthreads();

        // S = Q @ K^T; K-fragments via ldmatrix
        float facc[8][4];
#pragma unroll
        for (int j = 0; j < 8; j++)
#pragma unroll
            for (int r = 0; r < 4; r++) facc[j][r] = 0.f;
#pragma unroll
        for (int ks = 0; ks < 8; ks++) {
            uint32_t bf[4][4];
#pragma unroll
            for (int j2 = 0; j2 < 4; j2++)
                ldm_x4(bf[j2], kbase + ((j2 * 16 + frow) * KS_STR + ks * 16 + fcol) * 2);
#pragma unroll
            for (int j = 0; j < 8; j++)
                mma_f16(facc[j], qf[ks], bf[j >> 1][j & 1], bf[j >> 1][2 + (j & 1)]);
        }

        // online softmax in base-2 domain
        float mx0 = -1e30f, mx1 = -1e30f;
#pragma unroll
        for (int j = 0; j < 8; j++) {
            facc[j][0] *= scl2; facc[j][1] *= scl2;
            facc[j][2] *= scl2; facc[j][3] *= scl2;
            mx0 = fmaxf(mx0, fmaxf(facc[j][0], facc[j][1]));
            mx1 = fmaxf(mx1, fmaxf(facc[j][2], facc[j][3]));
        }
        mx0 = fmaxf(mx0, __shfl_xor_sync(0xffffffffu, mx0, 1));
        mx0 = fmaxf(mx0, __shfl_xor_sync(0xffffffffu, mx0, 2));
        mx1 = fmaxf(mx1, __shfl_xor_sync(0xffffffffu, mx1, 1));
        mx1 = fmaxf(mx1, __shfl_xor_sync(0xffffffffu, mx1, 2));
        const float mn0 = fmaxf(m0, mx0), mn1 = fmaxf(m1, mx1);

        uint32_t ph0[8], ph1[8];
        float ls0 = 0.f, ls1 = 0.f;
#pragma unroll
        for (int j = 0; j < 8; j++) {
            float p0 = exp2f(facc[j][0] - mn0);
            float p1 = exp2f(facc[j][1] - mn0);
            float p2 = exp2f(facc[j][2] - mn1);
            float p3 = exp2f(facc[j][3] - mn1);
            ph0[j] = packh2(p0, p1);
            ph1[j] = packh2(p2, p3);
            ls0 += p0 + p1; ls1 += p2 + p3;
        }
        ls0 += __shfl_xor_sync(0xffffffffu, ls0, 1);
        ls0 += __shfl_xor_sync(0xffffffffu, ls0, 2);
        ls1 += __shfl_xor_sync(0xffffffffu, ls1, 1);
        ls1 += __shfl_xor_sync(0xffffffffu, ls1, 2);

        const float a0 = exp2f(m0 - mn0), a1 = exp2f(m1 - mn1);
        l0 = l0 * a0 + ls0; l1 = l1 * a1 + ls1;
        m0 = mn0; m1 = mn1;
#pragma unroll
        for (int j = 0; j < 16; j++) {
            O[j][0] *= a0; O[j][1] *= a0;
            O[j][2] *= a1; O[j][3] *= a1;
        }

        // O += P @ V via ldmatrix.trans B-fragments
#pragma unroll
        for (int t = 0; t < 4; t++) {
            uint32_t af[4] = { ph0[2 * t], ph1[2 * t], ph0[2 * t + 1], ph1[2 * t + 1] };
#pragma unroll
            for (int jp = 0; jp < 8; jp++) {
                uint32_t bf[4];
                ldm_x4_trans(bf, vbase + (((t * 16 + vrow) * VS_STR) + jp * 16 + vcol) * 2);
                mma_f16(O[jp * 2 + 0], af, bf[0], bf[1]);
                mma_f16(O[jp * 2 + 1], af, bf[2], bf[3]);
            }
        }
        __syncthreads();
    }

    {
        const float il0 = 1.f / l0, il1 = 1.f / l1;
        const int r = q0 + w * 16 + rq;
#pragma unroll
        for (int j = 0; j < 16; j++) {
            const int c = h * 128 + j * 8 + kq * 2;
            *(uint32_t*)(heads + (size_t)r * D_DIM + c) = packh2(O[j][0] * il0, O[j][1] * il0);
            *(uint32_t*)(heads + (size_t)(r + 8) * D_DIM + c) = packh2(O[j][2] * il1, O[j][3] * il1);
        }
    }
}

// ---------------------------------------------------------------------------
// LayerNorm over D=2048: fp32 in, fp16 out
// ---------------------------------------------------------------------------
__global__ void __launch_bounds__(256) layernorm_h_kernel(
    const float* __restrict__ in, const float* __restrict__ gamma,
    const float* __restrict__ beta, __half* __restrict__ out)
{
    __shared__ float red[16];
    const int row = blockIdx.x;
    const int tid = threadIdx.x;
    const float* rp = in + (size_t)row * D_DIM;

    float v[8];
    float s = 0.f, sq = 0.f;
#pragma unroll
    for (int it = 0; it < 2; ++it) {
        float4 t = *(const float4*)(rp + tid * 4 + it * 1024);
        v[it * 4 + 0] = t.x; v[it * 4 + 1] = t.y;
        v[it * 4 + 2] = t.z; v[it * 4 + 3] = t.w;
    }
#pragma unroll
    for (int i = 0; i < 8; i++) { s += v[i]; sq += v[i] * v[i]; }
#pragma unroll
    for (int o = 16; o > 0; o >>= 1) {
        s  += __shfl_xor_sync(0xffffffffu, s, o);
        sq += __shfl_xor_sync(0xffffffffu, sq, o);
    }
    if ((tid & 31) == 0) { red[tid >> 5] = s; red[8 + (tid >> 5)] = sq; }
    __syncthreads();
    if (tid < 32) {
        float ss = (tid < 8) ? red[tid] : 0.f;
        float qq = (tid < 8) ? red[8 + tid] : 0.f;
#pragma unroll
        for (int o = 4; o > 0; o >>= 1) {
            ss += __shfl_xor_sync(0xffffffffu, ss, o);
            qq += __shfl_xor_sync(0xffffffffu, qq, o);
        }
        if (tid == 0) { red[0] = ss; red[1] = qq; }
    }
    __syncthreads();
    const float mu  = red[0] * (1.f / D_DIM);
    const float var = red[1] * (1.f / D_DIM) - mu * mu;
    const float rs  = rsqrtf(var + 1e-5f);
#pragma unroll
    for (int it = 0; it < 2; ++it) {
        const int c = tid * 4 + it * 1024;
        float4 g = *(const float4*)(gamma + c);
        float4 b = *(const float4*)(beta + c);
        uint2 o;
        o.x = packh2((v[it * 4 + 0] - mu) * rs * g.x + b.x,
                     (v[it * 4 + 1] - mu) * rs * g.y + b.y);
        o.y = packh2((v[it * 4 + 2] - mu) * rs * g.z + b.z,
                     (v[it * 4 + 3] - mu) * rs * g.w + b.w);
        *(uint2*)(out + (size_t)row * D_DIM + c) = o;
    }
}

// ---------------------------------------------------------------------------
// Launch
// ---------------------------------------------------------------------------
extern "C" void kernel_launch(void* const* d_in, const int* in_sizes, int n_in,
                              void* d_out, int out_size)
{
    const float* x     = (const float*)d_in[0];
    const float* Wq    = (const float*)d_in[1];
    const float* bq    = (const float*)d_in[2];
    const float* Wk    = (const float*)d_in[3];
    const float* bk    = (const float*)d_in[4];
    const float* Wv    = (const float*)d_in[5];
    const float* bv    = (const float*)d_in[6];
    const float* Wp    = (const float*)d_in[7];
    const float* bp    = (const float*)d_in[8];
    const float* W1    = (const float*)d_in[9];
    const float* b1    = (const float*)d_in[10];
    const float* W2    = (const float*)d_in[11];
    const float* b2    = (const float*)d_in[12];
    const float* gamma = (const float*)d_in[13];
    const float* beta  = (const float*)d_in[14];
    float* out = (float*)d_out;

    __half *xh, *qkv, *heads, *ln, *h1;
    float *proj, *bqkv;
    __half *wqkvt, *wpt, *w1t, *w2t;
    cudaGetSymbolAddress((void**)&xh,    g_xh);
    cudaGetSymbolAddress((void**)&qkv,   g_qkvh);
    cudaGetSymbolAddress((void**)&heads, g_headsh);
    cudaGetSymbolAddress((void**)&proj,  g_proj);
    cudaGetSymbolAddress((void**)&ln,    g_lnh);
    cudaGetSymbolAddress((void**)&h1,    g_h1h);
    cudaGetSymbolAddress((void**)&wqkvt, g_wqkvt);
    cudaGetSymbolAddress((void**)&bqkv,  g_bqkv);
    cudaGetSymbolAddress((void**)&wpt,   g_wpt);
    cudaGetSymbolAddress((void**)&w1t,   g_w1t);
    cudaGetSymbolAddress((void**)&w2t,   g_w2t);

    // ---- prep: x->fp16 + unified weight prep (1 launch) ----
    f2h_kernel<<<S_LEN * D_DIM / (256 * 8), 256>>>(x, xh);
    prep_weights_kernel<<<12312, dim3(32, 8)>>>(
        Wq, Wk, Wv, Wp, W1, W2, bq, bk, bv, wqkvt, wpt, w1t, w2t, bqkv);

    cudaFuncSetAttribute(gemm_h_kernel<0, 1>, cudaFuncAttributeMaxDynamicSharedMemorySize, GEMM_SMEM_BYTES);
    cudaFuncSetAttribute(gemm_h_kernel<1, 0>, cudaFuncAttributeMaxDynamicSharedMemorySize, GEMM_SMEM_BYTES);
    cudaFuncSetAttribute(gemm_h_kernel<2, 1>, cudaFuncAttributeMaxDynamicSharedMemorySize, GEMM_SMEM_BYTES);
    cudaFuncSetAttribute(gemm_h_kernel<0, 0>, cudaFuncAttributeMaxDynamicSharedMemorySize, GEMM_SMEM_BYTES);

    const dim3 blk(256);
    const dim3 g_qkv(QKV_LD / 128, S_LEN / 128);  // (48, 32)
    const dim3 g_dd(D_DIM / 128, S_LEN / 128);    // (16, 32)
    const dim3 g_f1(F_DIM / 128, S_LEN / 128);    // (64, 32)

    // fused QKV projection
    gemm_h_kernel<0, 1><<<g_qkv, blk, GEMM_SMEM_BYTES>>>(xh, wqkvt, bqkv, nullptr, qkv, S_LEN, QKV_LD, D_DIM);

    // flash attention
    cudaFuncSetAttribute(flash_attn_h_kernel,
                         cudaFuncAttributeMaxDynamicSharedMemorySize, FA_SMEM_BYTES);
    flash_attn_h_kernel<<<dim3(S_LEN / 128, H_NUM), blk, FA_SMEM_BYTES>>>(qkv, heads);

    // output projection + residual (fp32 x), LayerNorm
    gemm_h_kernel<1, 0><<<g_dd, blk, GEMM_SMEM_BYTES>>>(heads, wpt, bp, x, proj, S_LEN, D_DIM, D_DIM);
    layernorm_h_kernel<<<S_LEN, blk>>>(proj, gamma, beta, ln);

    // FFN
    gemm_h_kernel<2, 1><<<g_f1, blk, GEMM_SMEM_BYTES>>>(ln, w1t, b1, nullptr, h1, S_LEN, F_DIM, D_DIM);
    gemm_h_kernel<0, 0><<<g_dd, blk, GEMM_SMEM_BYTES>>>(h1, w2t, b2, nullptr, out, S_LEN, D_DIM, F_DIM);
}

// round 15
// speedup vs baseline: 1.1389x; 1.0574x over previous
#include <cuda_runtime.h>
#include <cuda_fp16.h>
#include <cstdint>

// Problem dims
#define S_LEN 4096
#define D_DIM 2048
#define H_NUM 16
#define F_DIM 8192
#define QKV_LD 6144

// ---------------------------------------------------------------------------
// Scratch (allocation is banned; use device globals)
// ---------------------------------------------------------------------------
__device__ __half g_xh[S_LEN * D_DIM];
__device__ __half g_qkvh[S_LEN * QKV_LD];
__device__ __half g_headsh[S_LEN * D_DIM];
__device__ float  g_proj[S_LEN * D_DIM];
__device__ __half g_lnh[S_LEN * D_DIM];
__device__ __half g_h1h[S_LEN * F_DIM];
// transposed fp16 weights, [N, K] row-major
__device__ __half g_wqkvt[3 * D_DIM * D_DIM];
__device__ float  g_bqkv[QKV_LD];
__device__ __half g_wpt[D_DIM * D_DIM];
__device__ __half g_w1t[F_DIM * D_DIM];
__device__ __half g_w2t[D_DIM * F_DIM];

// ---------------------------------------------------------------------------
// Portable PTX helpers (sm_80-level; tcgen05 is gated off on plain sm_103)
// ---------------------------------------------------------------------------
__device__ __forceinline__ uint32_t smem_u32(const void* p) {
    uint32_t a;
    asm("{ .reg .u64 t; cvta.to.shared.u64 t, %1; cvt.u32.u64 %0, t; }"
        : "=r"(a) : "l"(p));
    return a;
}

__device__ __forceinline__ uint32_t packh2(float a, float b) {
    __half2 h = __floats2half2_rn(a, b);
    return *reinterpret_cast<uint32_t*>(&h);
}

__device__ __forceinline__ void mma_f16(float* c, const uint32_t* a,
                                        uint32_t b0, uint32_t b1) {
    asm volatile(
        "mma.sync.aligned.m16n8k16.row.col.f32.f16.f16.f32 "
        "{%0,%1,%2,%3}, {%4,%5,%6,%7}, {%8,%9}, {%0,%1,%2,%3};"
        : "+f"(c[0]), "+f"(c[1]), "+f"(c[2]), "+f"(c[3])
        : "r"(a[0]), "r"(a[1]), "r"(a[2]), "r"(a[3]), "r"(b0), "r"(b1));
}

__device__ __forceinline__ void cp16(uint32_t saddr, const void* g) {
    asm volatile("cp.async.ca.shared.global [%0], [%1], 16;" :: "r"(saddr), "l"(g));
}
__device__ __forceinline__ void cp_commit() {
    asm volatile("cp.async.commit_group;" ::: "memory");
}
template <int N>
__device__ __forceinline__ void cp_wait() {
    asm volatile("cp.async.wait_group %0;" :: "n"(N) : "memory");
}

__device__ __forceinline__ void ldm_x4(uint32_t* r, uint32_t addr) {
    asm volatile("ldmatrix.sync.aligned.m8n8.x4.shared.b16 {%0,%1,%2,%3}, [%4];"
        : "=r"(r[0]), "=r"(r[1]), "=r"(r[2]), "=r"(r[3]) : "r"(addr));
}

__device__ __forceinline__ void ldm_x4_trans(uint32_t* r, uint32_t addr) {
    asm volatile("ldmatrix.sync.aligned.m8n8.x4.trans.shared.b16 {%0,%1,%2,%3}, [%4];"
        : "=r"(r[0]), "=r"(r[1]), "=r"(r[2]), "=r"(r[3]) : "r"(addr));
}

// ---------------------------------------------------------------------------
// fp16 warp-MMA GEMM, CTA 128x128, warp tile 32x64, BK=64, 2-stage cp.async.
// Round-9 proven configuration (2D grid, cp.async.ca). UNCHANGED.
//   EPI 0: +bias   EPI 1: +bias+res(fp32)   EPI 2: relu(+bias)
//   OH: 1 -> half output, 0 -> fp32 output
// ---------------------------------------------------------------------------
#define GSTR 72
#define STAGE_HALVES (2 * 128 * GSTR)            // A + B per stage
#define GEMM_SMEM_BYTES (2 * STAGE_HALVES * 2)   // 73728

template <int EPI, int OH>
__global__ void __launch_bounds__(256) gemm_h_kernel(
    const __half* __restrict__ A, const __half* __restrict__ Bt,
    const float* __restrict__ bias, const float* __restrict__ res,
    void* __restrict__ Cv, int M, int N, int K)
{
    extern __shared__ __half sh[];
    const uint32_t sbase = smem_u32(sh);

    float*  Cf = (float*)Cv;
    __half* Ch = (__half*)Cv;

    const int tid = threadIdx.x, lane = tid & 31, w = tid >> 5;
    const int wm = w >> 1, wn = w & 1;     // 4m x 2n; warp tile 32x64
    const int bm = blockIdx.y * 128, bn = blockIdx.x * 128;
    const int nk = K >> 6;

    const int crow = tid >> 3;        // 0..31
    const int ccol = (tid & 7) * 8;   // halves within 64-wide row

    auto load_stage = [&](int kt, int slot) {
        const int k0 = kt << 6;
        const uint32_t sa = sbase + slot * STAGE_HALVES * 2;
        const uint32_t sb = sa + 128 * GSTR * 2;
#pragma unroll
        for (int it = 0; it < 4; it++) {
            const int r = crow + it * 32;
            cp16(sa + (r * GSTR + ccol) * 2, A  + (size_t)(bm + r) * K + k0 + ccol);
            cp16(sb + (r * GSTR + ccol) * 2, Bt + (size_t)(bn + r) * K + k0 + ccol);
        }
    };

    float acc[2][8][4];
#pragma unroll
    for (int i = 0; i < 2; i++)
#pragma unroll
        for (int j = 0; j < 8; j++)
#pragma unroll
            for (int r = 0; r < 4; r++) acc[i][j][r] = 0.f;

    load_stage(0, 0); cp_commit();

    const int frow = lane & 15;
    const int fcol = (lane >> 4) * 8;

    for (int kt = 0; kt < nk; kt++) {
        cp_wait<0>();
        __syncthreads();
        if (kt + 1 < nk) { load_stage(kt + 1, (kt + 1) & 1); cp_commit(); }

        const uint32_t sa = sbase + (kt & 1) * STAGE_HALVES * 2;
        const uint32_t sb = sa + 128 * GSTR * 2;

#pragma unroll
        for (int kk = 0; kk < 4; kk++) {
            uint32_t af[2][4], bf[4][4];
#pragma unroll
            for (int i = 0; i < 2; i++)
                ldm_x4(af[i], sa + ((wm * 32 + i * 16 + frow) * GSTR + kk * 16 + fcol) * 2);
#pragma unroll
            for (int j2 = 0; j2 < 4; j2++)
                ldm_x4(bf[j2], sb + ((wn * 64 + j2 * 16 + frow) * GSTR + kk * 16 + fcol) * 2);
#pragma unroll
            for (int i = 0; i < 2; i++)
#pragma unroll
                for (int j = 0; j < 8; j++)
                    mma_f16(acc[i][j], af[i], bf[j >> 1][j & 1], bf[j >> 1][2 + (j & 1)]);
        }
    }

    // epilogue
#pragma unroll
    for (int i = 0; i < 2; i++) {
#pragma unroll
        for (int j = 0; j < 8; j++) {
            const int row = bm + wm * 32 + i * 16 + (lane >> 2);
            const int col = bn + wn * 64 + j * 8 + (lane & 3) * 2;
            const float2 bv = *(const float2*)(bias + col);
#pragma unroll
            for (int hf = 0; hf < 2; hf++) {
                const int r = row + hf * 8;
                float vx = acc[i][j][hf * 2 + 0] + bv.x;
                float vy = acc[i][j][hf * 2 + 1] + bv.y;
                if (EPI == 1) {
                    float2 rv = *(const float2*)(res + (size_t)r * N + col);
                    vx += rv.x; vy += rv.y;
                }
                if (EPI == 2) { vx = fmaxf(vx, 0.f); vy = fmaxf(vy, 0.f); }
                if (OH) {
                    *(uint32_t*)(Ch + (size_t)r * N + col) = packh2(vx, vy);
                } else {
                    float2 o = { vx, vy };
                    *(float2*)(Cf + (size_t)r * N + col) = o;
                }
            }
        }
    }
}

// ---------------------------------------------------------------------------
// fp32 -> fp16 bulk convert (x)
// ---------------------------------------------------------------------------
__global__ void __launch_bounds__(256) f2h_kernel(
    const float* __restrict__ in, __half* __restrict__ out)
{
    const size_t i = ((size_t)blockIdx.x * 256 + threadIdx.x) * 8;
    float4 a = *(const float4*)(in + i);
    float4 b = *(const float4*)(in + i + 4);
    uint4 o;
    o.x = packh2(a.x, a.y); o.y = packh2(a.z, a.w);
    o.z = packh2(b.x, b.y); o.w = packh2(b.z, b.w);
    *(uint4*)(out + i) = o;
}

// ---------------------------------------------------------------------------
// Unified weight prep: ALL transposes + bias concat in ONE launch (round 14).
// ---------------------------------------------------------------------------
__global__ void __launch_bounds__(256) prep_weights_kernel(
    const float* __restrict__ Wq, const float* __restrict__ Wk,
    const float* __restrict__ Wv, const float* __restrict__ Wp,
    const float* __restrict__ W1, const float* __restrict__ W2,
    const float* __restrict__ bq, const float* __restrict__ bk,
    const float* __restrict__ bv,
    __half* __restrict__ wqkvt, __half* __restrict__ wpt,
    __half* __restrict__ w1t,   __half* __restrict__ w2t,
    float* __restrict__ bqkv)
{
    const int bid = blockIdx.x;
    const int tid = threadIdx.y * 32 + threadIdx.x;

    if (bid >= 12288) {  // bias concat
        const int i = (bid - 12288) * 256 + tid;
        float v = (i < 2048) ? bq[i] : (i < 4096) ? bk[i - 2048] : bv[i - 4096];
        bqkv[i] = v;
        return;
    }

    const float* in;
    __half* out;
    int K, N, k0, n0;
    if (bid < 3072) {
        const int z = bid >> 6, t = bid & 63;
        const int which = z >> 4, hh = z & 15;
        in  = ((which == 0) ? Wq : (which == 1) ? Wk : Wv) + (size_t)hh * D_DIM * 128;
        out = wqkvt + (size_t)which * D_DIM * D_DIM + (size_t)hh * 128 * D_DIM;
        K = D_DIM; N = 128;
        n0 = (t & 1) * 64; k0 = (t >> 1) * 64;
    } else if (bid < 4096) {
        const int t = bid - 3072;
        in = Wp; out = wpt; K = D_DIM; N = D_DIM;
        n0 = (t & 31) * 64; k0 = (t >> 5) * 64;
    } else if (bid < 8192) {
        const int t = bid - 4096;
        in = W1; out = w1t; K = D_DIM; N = F_DIM;
        n0 = (t & 127) * 64; k0 = (t >> 7) * 64;
    } else {
        const int t = bid - 8192;
        in = W2; out = w2t; K = F_DIM; N = D_DIM;
        n0 = (t & 31) * 64; k0 = (t >> 5) * 64;
    }

    __shared__ float t[64][65];
    const int tx = threadIdx.x, ty = threadIdx.y;
#pragma unroll
    for (int i = 0; i < 64; i += 8) {
        t[ty + i][tx]      = in[(size_t)(k0 + ty + i) * N + n0 + tx];
        t[ty + i][tx + 32] = in[(size_t)(k0 + ty + i) * N + n0 + tx + 32];
    }
    __syncthreads();
#pragma unroll
    for (int i = 0; i < 64; i += 8) {
        const int n = n0 + ty + i;
        __half2 v = __floats2half2_rn(t[2 * tx][ty + i], t[2 * tx + 1][ty + i]);
        *(__half2*)(out + (size_t)n * K + k0 + 2 * tx) = v;
    }
}

// ---------------------------------------------------------------------------
// Flash attention, fp16 mma, FA2-style.
// NEW: __launch_bounds__(256, 2) for 2 CTAs/SM (was reg-limited to 1 at 171
// regs). Q fragments reloaded per-iter via ldmatrix from the resident Q smem
// tile instead of being cached in 32 registers.
// ---------------------------------------------------------------------------
#define QS_STR 136
#define KS_STR 136
#define VS_STR 136
#define FA_SMEM_BYTES ((128 * QS_STR + 64 * KS_STR + 64 * VS_STR) * 2)  // 69632

__global__ void __launch_bounds__(256, 2) flash_attn_h_kernel(
    const __half* __restrict__ qkv, __half* __restrict__ heads)
{
    extern __shared__ __half smh[];
    __half* Qs  = smh;
    __half* Ks  = Qs + 128 * QS_STR;
    __half* Vs  = Ks + 64 * KS_STR;
    const uint32_t qbase = smem_u32(Qs);
    const uint32_t kbase = smem_u32(Ks);
    const uint32_t vbase = smem_u32(Vs);

    const __half* qb = qkv;
    const __half* kb = qkv + 2048;
    const __half* vb = qkv + 4096;

    const int h   = blockIdx.y;
    const int q0  = blockIdx.x * 128;
    const int tid = threadIdx.x, lane = tid & 31, w = tid >> 5;
    const int rq = lane >> 2, kq = lane & 3;
    const int frow = lane & 15;
    const int fcol = (lane >> 4) * 8;
    // scale * log2(e): softmax computed in base-2 domain
    const float scl2 = 0.08838834764831845f * 1.4426950408889634f;

    {
        int idx = tid * 8;
#pragma unroll
        for (int it = 0; it < 8; it++) {
            int r = idx >> 7, c = idx & 127;
            *(uint4*)(Qs + r * QS_STR + c) =
                *(const uint4*)(qb + (size_t)(q0 + r) * QKV_LD + h * 128 + c);
            idx += 2048;
        }
    }
    __syncthreads();

    // Q fragment ldmatrix base address (per ks step: + ks*16 halves)
    const uint32_t qfrag = qbase + ((w * 16 + frow) * QS_STR + fcol) * 2;

    float O[16][4];
#pragma unroll
    for (int j = 0; j < 16; j++)
#pragma unroll
        for (int r = 0; r < 4; r++) O[j][r] = 0.f;
    float m0 = -1e30f, m1 = -1e30f, l0 = 0.f, l1 = 0.f;

    const uint32_t vrow = lane & 15;
    const uint32_t vcol = (lane >> 4) * 8;

    for (int kblk = 0; kblk < 64; kblk++) {
        {
            int idx = tid * 8;
#pragma unroll
            for (int it = 0; it < 4; it++) {
                int r = idx >> 7, c = idx & 127;
                *(uint4*)(Ks + r * KS_STR + c) =
                    *(const uint4*)(kb + (size_t)(kblk * 64 + r) * QKV_LD + h * 128 + c);
                *(uint4*)(Vs + r * VS_STR + c) =
                    *(const uint4*)(vb + (size_t)(kblk * 64 + r) * QKV_LD + h * 128 + c);
                idx += 2048;
            }
        }
        __syncthreads();

        // S = Q @ K^T; Q and K fragments both via ldmatrix
        float facc[8][4];
#pragma unroll
        for (int j = 0; j < 8; j++)
#pragma unroll
            for (int r = 0; r < 4; r++) facc[j][r] = 0.f;
#pragma unroll
        for (int ks = 0; ks < 8; ks++) {
            uint32_t af[4], bf[4][4];
            ldm_x4(af, qfrag + ks * 32);   // 16 halves = 32 bytes
#pragma unroll
            for (int j2 = 0; j2 < 4; j2++)
                ldm_x4(bf[j2], kbase + ((j2 * 16 + frow) * KS_STR + ks * 16 + fcol) * 2);
#pragma unroll
            for (int j = 0; j < 8; j++)
                mma_f16(facc[j], af, bf[j >> 1][j & 1], bf[j >> 1][2 + (j & 1)]);
        }

        // online softmax in base-2 domain
        float mx0 = -1e30f, mx1 = -1e30f;
#pragma unroll
        for (int j = 0; j < 8; j++) {
            facc[j][0] *= scl2; facc[j][1] *= scl2;
            facc[j][2] *= scl2; facc[j][3] *= scl2;
            mx0 = fmaxf(mx0, fmaxf(facc[j][0], facc[j][1]));
            mx1 = fmaxf(mx1, fmaxf(facc[j][2], facc[j][3]));
        }
        mx0 = fmaxf(mx0, __shfl_xor_sync(0xffffffffu, mx0, 1));
        mx0 = fmaxf(mx0, __shfl_xor_sync(0xffffffffu, mx0, 2));
        mx1 = fmaxf(mx1, __shfl_xor_sync(0xffffffffu, mx1, 1));
        mx1 = fmaxf(mx1, __shfl_xor_sync(0xffffffffu, mx1, 2));
        const float mn0 = fmaxf(m0, mx0), mn1 = fmaxf(m1, mx1);

        uint32_t ph0[8], ph1[8];
        float ls0 = 0.f, ls1 = 0.f;
#pragma unroll
        for (int j = 0; j < 8; j++) {
            float p0 = exp2f(facc[j][0] - mn0);
            float p1 = exp2f(facc[j][1] - mn0);
            float p2 = exp2f(facc[j][2] - mn1);
            float p3 = exp2f(facc[j][3] - mn1);
            ph0[j] = packh2(p0, p1);
            ph1[j] = packh2(p2, p3);
            ls0 += p0 + p1; ls1 += p2 + p3;
        }
        ls0 += __shfl_xor_sync(0xffffffffu, ls0, 1);
        ls0 += __shfl_xor_sync(0xffffffffu, ls0, 2);
        ls1 += __shfl_xor_sync(0xffffffffu, ls1, 1);
        ls1 += __shfl_xor_sync(0xffffffffu, ls1, 2);

        const float a0 = exp2f(m0 - mn0), a1 = exp2f(m1 - mn1);
        l0 = l0 * a0 + ls0; l1 = l1 * a1 + ls1;
        m0 = mn0; m1 = mn1;
#pragma unroll
        for (int j = 0; j < 16; j++) {
            O[j][0] *= a0; O[j][1] *= a0;
            O[j][2] *= a1; O[j][3] *= a1;
        }

        // O += P @ V via ldmatrix.trans B-fragments
#pragma unroll
        for (int t = 0; t < 4; t++) {
            uint32_t af[4] = { ph0[2 * t], ph1[2 * t], ph0[2 * t + 1], ph1[2 * t + 1] };
#pragma unroll
            for (int jp = 0; jp < 8; jp++) {
                uint32_t bf[4];
                ldm_x4_trans(bf, vbase + (((t * 16 + vrow) * VS_STR) + jp * 16 + vcol) * 2);
                mma_f16(O[jp * 2 + 0], af, bf[0], bf[1]);
                mma_f16(O[jp * 2 + 1], af, bf[2], bf[3]);
            }
        }
        __syncthreads();
    }

    {
        const float il0 = 1.f / l0, il1 = 1.f / l1;
        const int r = q0 + w * 16 + rq;
#pragma unroll
        for (int j = 0; j < 16; j++) {
            const int c = h * 128 + j * 8 + kq * 2;
            *(uint32_t*)(heads + (size_t)r * D_DIM + c) = packh2(O[j][0] * il0, O[j][1] * il0);
            *(uint32_t*)(heads + (size_t)(r + 8) * D_DIM + c) = packh2(O[j][2] * il1, O[j][3] * il1);
        }
    }
}

// ---------------------------------------------------------------------------
// LayerNorm over D=2048: fp32 in, fp16 out
// ---------------------------------------------------------------------------
__global__ void __launch_bounds__(256) layernorm_h_kernel(
    const float* __restrict__ in, const float* __restrict__ gamma,
    const float* __restrict__ beta, __half* __restrict__ out)
{
    __shared__ float red[16];
    const int row = blockIdx.x;
    const int tid = threadIdx.x;
    const float* rp = in + (size_t)row * D_DIM;

    float v[8];
    float s = 0.f, sq = 0.f;
#pragma unroll
    for (int it = 0; it < 2; ++it) {
        float4 t = *(const float4*)(rp + tid * 4 + it * 1024);
        v[it * 4 + 0] = t.x; v[it * 4 + 1] = t.y;
        v[it * 4 + 2] = t.z; v[it * 4 + 3] = t.w;
    }
#pragma unroll
    for (int i = 0; i < 8; i++) { s += v[i]; sq += v[i] * v[i]; }
#pragma unroll
    for (int o = 16; o > 0; o >>= 1) {
        s  += __shfl_xor_sync(0xffffffffu, s, o);
        sq += __shfl_xor_sync(0xffffffffu, sq, o);
    }
    if ((tid & 31) == 0) { red[tid >> 5] = s; red[8 + (tid >> 5)] = sq; }
    __syncthreads();
    if (tid < 32) {
        float ss = (tid < 8) ? red[tid] : 0.f;
        float qq = (tid < 8) ? red[8 + tid] : 0.f;
#pragma unroll
        for (int o = 4; o > 0; o >>= 1) {
            ss += __shfl_xor_sync(0xffffffffu, ss, o);
            qq += __shfl_xor_sync(0xffffffffu, qq, o);
        }
        if (tid == 0) { red[0] = ss; red[1] = qq; }
    }
    __syncthreads();
    const float mu  = red[0] * (1.f / D_DIM);
    const float var = red[1] * (1.f / D_DIM) - mu * mu;
    const float rs  = rsqrtf(var + 1e-5f);
#pragma unroll
    for (int it = 0; it < 2; ++it) {
        const int c = tid * 4 + it * 1024;
        float4 g = *(const float4*)(gamma + c);
        float4 b = *(const float4*)(beta + c);
        uint2 o;
        o.x = packh2((v[it * 4 + 0] - mu) * rs * g.x + b.x,
                     (v[it * 4 + 1] - mu) * rs * g.y + b.y);
        o.y = packh2((v[it * 4 + 2] - mu) * rs * g.z + b.z,
                     (v[it * 4 + 3] - mu) * rs * g.w + b.w);
        *(uint2*)(out + (size_t)row * D_DIM + c) = o;
    }
}

// ---------------------------------------------------------------------------
// Launch
// ---------------------------------------------------------------------------
extern "C" void kernel_launch(void* const* d_in, const int* in_sizes, int n_in,
                              void* d_out, int out_size)
{
    const float* x     = (const float*)d_in[0];
    const float* Wq    = (const float*)d_in[1];
    const float* bq    = (const float*)d_in[2];
    const float* Wk    = (const float*)d_in[3];
    const float* bk    = (const float*)d_in[4];
    const float* Wv    = (const float*)d_in[5];
    const float* bv    = (const float*)d_in[6];
    const float* Wp    = (const float*)d_in[7];
    const float* bp    = (const float*)d_in[8];
    const float* W1    = (const float*)d_in[9];
    const float* b1    = (const float*)d_in[10];
    const float* W2    = (const float*)d_in[11];
    const float* b2    = (const float*)d_in[12];
    const float* gamma = (const float*)d_in[13];
    const float* beta  = (const float*)d_in[14];
    float* out = (float*)d_out;

    __half *xh, *qkv, *heads, *ln, *h1;
    float *proj, *bqkv;
    __half *wqkvt, *wpt, *w1t, *w2t;
    cudaGetSymbolAddress((void**)&xh,    g_xh);
    cudaGetSymbolAddress((void**)&qkv,   g_qkvh);
    cudaGetSymbolAddress((void**)&heads, g_headsh);
    cudaGetSymbolAddress((void**)&proj,  g_proj);
    cudaGetSymbolAddress((void**)&ln,    g_lnh);
    cudaGetSymbolAddress((void**)&h1,    g_h1h);
    cudaGetSymbolAddress((void**)&wqkvt, g_wqkvt);
    cudaGetSymbolAddress((void**)&bqkv,  g_bqkv);
    cudaGetSymbolAddress((void**)&wpt,   g_wpt);
    cudaGetSymbolAddress((void**)&w1t,   g_w1t);
    cudaGetSymbolAddress((void**)&w2t,   g_w2t);

    // ---- prep: x->fp16 + unified weight prep ----
    f2h_kernel<<<S_LEN * D_DIM / (256 * 8), 256>>>(x, xh);
    prep_weights_kernel<<<12312, dim3(32, 8)>>>(
        Wq, Wk, Wv, Wp, W1, W2, bq, bk, bv, wqkvt, wpt, w1t, w2t, bqkv);

    cudaFuncSetAttribute(gemm_h_kernel<0, 1>, cudaFuncAttributeMaxDynamicSharedMemorySize, GEMM_SMEM_BYTES);
    cudaFuncSetAttribute(gemm_h_kernel<1, 0>, cudaFuncAttributeMaxDynamicSharedMemorySize, GEMM_SMEM_BYTES);
    cudaFuncSetAttribute(gemm_h_kernel<2, 1>, cudaFuncAttributeMaxDynamicSharedMemorySize, GEMM_SMEM_BYTES);
    cudaFuncSetAttribute(gemm_h_kernel<0, 0>, cudaFuncAttributeMaxDynamicSharedMemorySize, GEMM_SMEM_BYTES);

    const dim3 blk(256);
    const dim3 g_qkv(QKV_LD / 128, S_LEN / 128);  // (48, 32)
    const dim3 g_dd(D_DIM / 128, S_LEN / 128);    // (16, 32)
    const dim3 g_f1(F_DIM / 128, S_LEN / 128);    // (64, 32)

    // fused QKV projection
    gemm_h_kernel<0, 1><<<g_qkv, blk, GEMM_SMEM_BYTES>>>(xh, wqkvt, bqkv, nullptr, qkv, S_LEN, QKV_LD, D_DIM);

    // flash attention
    cudaFuncSetAttribute(flash_attn_h_kernel,
                         cudaFuncAttributeMaxDynamicSharedMemorySize, FA_SMEM_BYTES);
    flash_attn_h_kernel<<<dim3(S_LEN / 128, H_NUM), blk, FA_SMEM_BYTES>>>(qkv, heads);

    // output projection + residual (fp32 x), LayerNorm
    gemm_h_kernel<1, 0><<<g_dd, blk, GEMM_SMEM_BYTES>>>(heads, wpt, bp, x, proj, S_LEN, D_DIM, D_DIM);
    layernorm_h_kernel<<<S_LEN, blk>>>(proj, gamma, beta, ln);

    // FFN
    gemm_h_kernel<2, 1><<<g_f1, blk, GEMM_SMEM_BYTES>>>(ln, w1t, b1, nullptr, h1, S_LEN, F_DIM, D_DIM);
    gemm_h_kernel<0, 0><<<g_dd, blk, GEMM_SMEM_BYTES>>>(h1, w2t, b2, nullptr, out, S_LEN, D_DIM, F_DIM);
}